// round 2
// baseline (speedup 1.0000x reference)
#include <cuda_runtime.h>
#include <math.h>

#define BB 2
#define CC 256
#define DD 32
#define HH 64
#define WW 192
#define HWs 12288        // H*W
#define KSTR 193         // k/v row stride in smem (192 + replicated border col)

typedef unsigned long long ull;

// ---------------- packed f32x2 helpers (Blackwell FFMA2) ----------------
__device__ __forceinline__ ull f2_pack(float lo, float hi) {
    ull r;
    asm("mov.b64 %0, {%1, %2};" : "=l"(r) : "f"(lo), "f"(hi));
    return r;
}
__device__ __forceinline__ void f2_unpack(ull v, float& lo, float& hi) {
    asm("mov.b64 {%0, %1}, %2;" : "=f"(lo), "=f"(hi) : "l"(v));
}
__device__ __forceinline__ void f2_fma(ull& d, ull a, ull b) {
    asm("fma.rn.f32x2 %0, %1, %2, %0;" : "+l"(d) : "l"(a), "l"(b));
}

// ---------------- scratch (device globals; no allocation allowed) ----------------
__device__ float g_q   [BB * 64 * HWs];
__device__ float g_k   [BB * 64 * HWs];
__device__ float g_v   [BB * 64 * HWs];
__device__ float g_agg [BB * 64 * HWs];
__device__ float g_h1  [BB * 64 * HWs];
__device__ float g_cost[BB * 32 * HWs];
__device__ float g_norm[BB * 32 * HWs];

// =================================================================================
// GEMM for q/k/v:  Y[b][m][n] = sum_k A[m][k] * X[b][k][n] + bias[m]
// M=64, K=256, N=12288.  BM=64, BN=64, BK=16, 128 threads, 4x8 register tile,
// FFMA2 over n-pairs.
// =================================================================================
__global__ void gemm_qkv_kernel(const float* __restrict__ A,
                                const float* __restrict__ bias,
                                const float* __restrict__ X,
                                float* __restrict__ Y) {
    __shared__ __align__(16) float As[16 * 68];   // [k][m]
    __shared__ __align__(16) float Bs[16 * 64];   // [k][n]

    const int b   = blockIdx.z;
    const int n0  = blockIdx.x * 64;
    const int tid = threadIdx.x;
    const int trow = tid >> 3;      // 0..15
    const int tcol = tid & 7;       // 0..7

    const float* Xb = X + (size_t)b * CC * HWs;

    ull acc[4][4];
#pragma unroll
    for (int i = 0; i < 4; ++i)
#pragma unroll
        for (int j = 0; j < 4; ++j) acc[i][j] = 0ull;

    for (int k0 = 0; k0 < 256; k0 += 16) {
#pragma unroll
        for (int i = 0; i < 8; ++i) {           // A tile: 64x16
            int idx = i * 128 + tid;
            int m = idx >> 4, k = idx & 15;
            As[k * 68 + m] = A[m * 256 + k0 + k];
        }
#pragma unroll
        for (int i = 0; i < 8; ++i) {           // B tile: 16x64
            int idx = i * 128 + tid;
            int k = idx >> 6, n = idx & 63;
            Bs[k * 64 + n] = Xb[(size_t)(k0 + k) * HWs + n0 + n];
        }
        __syncthreads();
#pragma unroll
        for (int kk = 0; kk < 16; ++kk) {
            ull a2[4], bv2[4];
            const ull* brow = reinterpret_cast<const ull*>(&Bs[kk * 64 + tcol * 8]);
#pragma unroll
            for (int j = 0; j < 4; ++j) bv2[j] = brow[j];
#pragma unroll
            for (int i = 0; i < 4; ++i) {
                float av = As[kk * 68 + trow * 4 + i];
                a2[i] = f2_pack(av, av);
            }
#pragma unroll
            for (int i = 0; i < 4; ++i)
#pragma unroll
                for (int j = 0; j < 4; ++j) f2_fma(acc[i][j], a2[i], bv2[j]);
        }
        __syncthreads();
    }
#pragma unroll
    for (int i = 0; i < 4; ++i) {
        int m = trow * 4 + i;
        float bi = bias[m];
        float* dst = Y + ((size_t)(b * 64 + m)) * HWs + n0 + tcol * 8;
#pragma unroll
        for (int j = 0; j < 4; ++j) {
            float v0, v1;
            f2_unpack(acc[i][j], v0, v1);
            dst[2 * j]     = v0 + bi;
            dst[2 * j + 1] = v1 + bi;
        }
    }
}

// =================================================================================
// Final GEMM: out[b][m][n] = elu( sum_{k<256} rw[m][k]*t_feat[b][k][n]
//                                + sum_{k>=256} rw[m][k]*norm[b][k-256][n] + rb[m] )
// M=256, K=288, N=12288.
// =================================================================================
__global__ void gemm_final_kernel(const float* __restrict__ A,      // rw [256][288]
                                  const float* __restrict__ bias,   // rb [256]
                                  const float* __restrict__ tfeat,
                                  const float* __restrict__ nrm,
                                  float* __restrict__ Y) {
    __shared__ __align__(16) float As[16 * 68];
    __shared__ __align__(16) float Bs[16 * 64];

    const int b   = blockIdx.z;
    const int n0  = blockIdx.x * 64;
    const int m0  = blockIdx.y * 64;
    const int tid = threadIdx.x;
    const int trow = tid >> 3;
    const int tcol = tid & 7;

    ull acc[4][4];
#pragma unroll
    for (int i = 0; i < 4; ++i)
#pragma unroll
        for (int j = 0; j < 4; ++j) acc[i][j] = 0ull;

    for (int k0 = 0; k0 < 288; k0 += 16) {
#pragma unroll
        for (int i = 0; i < 8; ++i) {
            int idx = i * 128 + tid;
            int m = idx >> 4, k = idx & 15;
            As[k * 68 + m] = A[(m0 + m) * 288 + k0 + k];
        }
#pragma unroll
        for (int i = 0; i < 8; ++i) {
            int idx = i * 128 + tid;
            int k = idx >> 6, n = idx & 63;
            int kg = k0 + k;
            const float* src = (kg < 256)
                ? (tfeat + ((size_t)(b * 256 + kg)) * HWs)
                : (nrm + ((size_t)(b * 32 + (kg - 256))) * HWs);
            Bs[k * 64 + n] = src[n0 + n];
        }
        __syncthreads();
#pragma unroll
        for (int kk = 0; kk < 16; ++kk) {
            ull a2[4], bv2[4];
            const ull* brow = reinterpret_cast<const ull*>(&Bs[kk * 64 + tcol * 8]);
#pragma unroll
            for (int j = 0; j < 4; ++j) bv2[j] = brow[j];
#pragma unroll
            for (int i = 0; i < 4; ++i) {
                float av = As[kk * 68 + trow * 4 + i];
                a2[i] = f2_pack(av, av);
            }
#pragma unroll
            for (int i = 0; i < 4; ++i)
#pragma unroll
                for (int j = 0; j < 4; ++j) f2_fma(acc[i][j], a2[i], bv2[j]);
        }
        __syncthreads();
    }
#pragma unroll
    for (int i = 0; i < 4; ++i) {
        int m = m0 + trow * 4 + i;
        float bi = bias[m];
        float* dst = Y + ((size_t)(b * 256 + m)) * HWs + n0 + tcol * 8;
#pragma unroll
        for (int j = 0; j < 4; ++j) {
            float v0, v1;
            f2_unpack(acc[i][j], v0, v1);
            v0 += bi; v1 += bi;
            v0 = v0 > 0.f ? v0 : (expf(v0) - 1.f);
            v1 = v1 > 0.f ? v1 : (expf(v1) - 1.f);
            dst[2 * j]     = v0;
            dst[2 * j + 1] = v1;
        }
    }
}

// =================================================================================
// Fused warp + cost + softmax + aggregation.
// One block per (h, b). 192 threads, thread = output column w.
// =================================================================================
__global__ void attn_kernel(const float* __restrict__ gq,
                            const float* __restrict__ gk,
                            const float* __restrict__ gv,
                            const float* __restrict__ directs,
                            const int*   __restrict__ img_w_i,
                            float* __restrict__ gcost,
                            float* __restrict__ gagg) {
    extern __shared__ float sm[];
    float* ks = sm;                       // 64*193
    float* vs = ks + 64 * KSTR;           // 64*193
    float* qs = vs + 64 * KSTR;           // 64*192

    const int h = blockIdx.x;
    const int b = blockIdx.y;
    const int w = threadIdx.x;            // 0..191

    for (int c = 0; c < 64; ++c) {
        size_t off = ((size_t)(b * 64 + c)) * HWs + h * WW + w;
        float kv = gk[off];
        float vv = gv[off];
        qs[c * WW + w]   = gq[off];
        ks[c * KSTR + w] = kv;
        vs[c * KSTR + w] = vv;
        if (w == WW - 1) {                // replicate border for x1 = x0+1
            ks[c * KSTR + WW] = kv;
            vs[c * KSTR + WW] = vv;
        }
    }

    // shift step: disps[d]*rel_scale*directs[b]*(W-1), disps[d]=d*0.01
    int iv = img_w_i[0];
    float imw = (iv > 0 && iv < 1000000) ? (float)iv : __int_as_float(iv);
    float ss = directs[b] * (640.0f / imw) * (0.01f * (float)(WW - 1));

    int   ix[DD];
    float fr[DD];
#pragma unroll
    for (int d = 0; d < DD; ++d) {
        float src = fminf(fmaxf((float)w + ss * (float)d, 0.0f), (float)(WW - 1));
        float x0 = floorf(src);
        ix[d] = (int)x0;
        fr[d] = src - x0;
    }
    __syncthreads();

    float cost[DD];
#pragma unroll
    for (int d = 0; d < DD; ++d) cost[d] = 0.f;

    for (int c = 0; c < 64; ++c) {
        const float* kr = ks + c * KSTR;
        float qc = qs[c * WW + w];
#pragma unroll
        for (int d = 0; d < DD; ++d) {
            float k0 = kr[ix[d]];
            float k1 = kr[ix[d] + 1];
            cost[d] += qc * (k0 + fr[d] * (k1 - k0));
        }
    }
#pragma unroll
    for (int d = 0; d < DD; ++d) {
        cost[d] *= 0.125f;                // 1/sqrt(64)
        gcost[((size_t)(b * 32 + d)) * HWs + h * WW + w] = cost[d];
    }

    float mx = cost[0];
#pragma unroll
    for (int d = 1; d < DD; ++d) mx = fmaxf(mx, cost[d]);
    float s = 0.f;
#pragma unroll
    for (int d = 0; d < DD; ++d) { cost[d] = expf(cost[d] - mx); s += cost[d]; }
    float inv = 1.0f / s;
#pragma unroll
    for (int d = 0; d < DD; ++d) cost[d] *= inv;

    for (int c = 0; c < 64; ++c) {
        const float* vr = vs + c * KSTR;
        float acc = 0.f;
#pragma unroll
        for (int d = 0; d < DD; ++d) {
            float v0 = vr[ix[d]];
            float v1 = vr[ix[d] + 1];
            acc += cost[d] * (v0 + fr[d] * (v1 - v0));
        }
        gagg[((size_t)(b * 64 + c)) * HWs + h * WW + w] = acc;
    }
}

// =================================================================================
// conv3x3 #1: in = concat[q(64), agg(64)] -> 128 ch, out 64 ch, ELU, FFMA2.
// Tile 16w x 11h pixels, grid (12, 6, B) = 144 blocks (~all SMs).
// 256 threads = 4 ocg(16 oc = 8 oc-pairs) x 64 pixel-groups (3 px each; 176 used).
// =================================================================================
__global__ void conv1_kernel(const float* __restrict__ gq,
                             const float* __restrict__ gagg,
                             const float* __restrict__ wgt,   // [64][128][3][3]
                             const float* __restrict__ bias,  // [64]
                             float* __restrict__ out) {
    __shared__ __align__(16) float in_s[8 * 234];  // 8 ic x 13x18 halo
    __shared__ __align__(16) float w_s[72 * 66];   // [t=ic*9+r9][oc], pad 66 (8B ok)

    const int b   = blockIdx.z;
    const int y0  = blockIdx.y * 11;
    const int tx0 = blockIdx.x * 16;
    const int tid = threadIdx.x;
    const int ocg = tid >> 6;            // 0..3
    const int pix = tid & 63;            // 0..63

    int py_[3], px_[3];
    bool val_[3];
#pragma unroll
    for (int k = 0; k < 3; ++k) {
        int l = pix + 64 * k;
        py_[k] = l >> 4;
        px_[k] = l & 15;
        val_[k] = (l < 176);
    }

    ull acc[3][8];
#pragma unroll
    for (int k = 0; k < 3; ++k)
#pragma unroll
        for (int j = 0; j < 8; ++j) acc[k][j] = 0ull;

    for (int c0 = 0; c0 < 128; c0 += 8) {
        __syncthreads();
        // stage input chunk (zero-padded halo), 8 ic x 13 x 18
        for (int idx = tid; idx < 8 * 234; idx += 256) {
            int ic = idx / 234;
            int r  = idx - ic * 234;
            int yy = r / 18, xx = r - yy * 18;
            int gy = y0 + yy - 1, gx = tx0 + xx - 1;
            float v = 0.f;
            if ((unsigned)gy < (unsigned)HH && (unsigned)gx < (unsigned)WW) {
                int icg = c0 + ic;
                const float* src = (icg < 64)
                    ? (gq + ((size_t)(b * 64 + icg)) * HWs)
                    : (gagg + ((size_t)(b * 64 + icg - 64)) * HWs);
                v = src[gy * WW + gx];
            }
            in_s[idx] = v;
        }
        // stage weight chunk
        for (int idx = tid; idx < 64 * 72; idx += 256) {
            int oc = idx / 72, t = idx - oc * 72;
            int ic = t / 9,  r9 = t - ic * 9;
            w_s[t * 66 + oc] = wgt[((oc * 128) + c0 + ic) * 9 + r9];
        }
        __syncthreads();

#pragma unroll 1
        for (int ic = 0; ic < 8; ++ic) {
#pragma unroll
            for (int ky = 0; ky < 3; ++ky)
#pragma unroll
            for (int kx = 0; kx < 3; ++kx) {
                int t = ic * 9 + ky * 3 + kx;
                const ull* wrow = reinterpret_cast<const ull*>(&w_s[t * 66 + ocg * 16]);
                ull wv2[8];
#pragma unroll
                for (int j = 0; j < 8; ++j) wv2[j] = wrow[j];
#pragma unroll
                for (int k = 0; k < 3; ++k) {
                    float ivv = val_[k]
                        ? in_s[ic * 234 + (py_[k] + ky) * 18 + px_[k] + kx] : 0.f;
                    ull iv2 = f2_pack(ivv, ivv);
#pragma unroll
                    for (int j = 0; j < 8; ++j) f2_fma(acc[k][j], iv2, wv2[j]);
                }
            }
        }
    }
#pragma unroll
    for (int k = 0; k < 3; ++k) {
        int gy = y0 + py_[k], gx = tx0 + px_[k];
        if (!val_[k] || gy >= HH) continue;
#pragma unroll
        for (int j = 0; j < 8; ++j) {
            int oc = ocg * 16 + 2 * j;
            float v0, v1;
            f2_unpack(acc[k][j], v0, v1);
            v0 += bias[oc];
            v1 += bias[oc + 1];
            v0 = v0 > 0.f ? v0 : (expf(v0) - 1.f);
            v1 = v1 > 0.f ? v1 : (expf(v1) - 1.f);
            out[((size_t)(b * 64 + oc)) * HWs + gy * WW + gx]       = v0;
            out[((size_t)(b * 64 + oc + 1)) * HWs + gy * WW + gx]   = v1;
        }
    }
}

// =================================================================================
// conv3x3 #2 (64 -> 32) FFMA2, FUSED with: cost = 0.5*(cost_old + res),
// write final cost, softmax over d, write norm.
// Tile 16x16 px, 256 threads = 2 ocg(16 oc = 8 pairs) x 128 px-groups (2 px).
// smem exchange before epilogue so each thread owns a full 32-d pixel.
// =================================================================================
__global__ void conv2_kernel(const float* __restrict__ h1,
                             const float* __restrict__ wgt,   // [32][64][3][3]
                             const float* __restrict__ bias,  // [32]
                             const float* __restrict__ gcost,
                             float* __restrict__ out_cost,
                             float* __restrict__ gnorm) {
    // one buffer: staging phase uses [in_s | w_s], exchange phase reuses it all
    __shared__ __align__(16) float buf[256 * 33];   // 8448 floats >= 2592+2448
    float* in_s = buf;                // 8*324
    float* w_s  = buf + 8 * 324;      // 72*34 (pad 34 -> 8B-aligned rows)

    const int b   = blockIdx.z;
    const int ty0 = blockIdx.y * 16;
    const int tx0 = blockIdx.x * 16;
    const int tid = threadIdx.x;         // 0..255
    const int ocg  = tid >> 7;           // 0..1 (16 oc each)
    const int pixg = tid & 127;          // 0..127

    ull acc[2][8];
#pragma unroll
    for (int k = 0; k < 2; ++k)
#pragma unroll
        for (int j = 0; j < 8; ++j) acc[k][j] = 0ull;

    for (int c0 = 0; c0 < 64; c0 += 8) {
        __syncthreads();
        for (int idx = tid; idx < 8 * 324; idx += 256) {
            int ic = idx / 324;
            int r  = idx - ic * 324;
            int yy = r / 18, xx = r - yy * 18;
            int gy = ty0 + yy - 1, gx = tx0 + xx - 1;
            float v = 0.f;
            if ((unsigned)gy < (unsigned)HH && (unsigned)gx < (unsigned)WW) {
                v = h1[((size_t)(b * 64 + c0 + ic)) * HWs + gy * WW + gx];
            }
            in_s[idx] = v;
        }
        for (int idx = tid; idx < 32 * 72; idx += 256) {
            int oc = idx / 72, t = idx - oc * 72;
            int ic = t / 9,  r9 = t - ic * 9;
            w_s[t * 34 + oc] = wgt[((oc * 64) + c0 + ic) * 9 + r9];
        }
        __syncthreads();

#pragma unroll 1
        for (int ic = 0; ic < 8; ++ic) {
#pragma unroll
            for (int ky = 0; ky < 3; ++ky)
#pragma unroll
            for (int kx = 0; kx < 3; ++kx) {
                int t = ic * 9 + ky * 3 + kx;
                const ull* wrow = reinterpret_cast<const ull*>(&w_s[t * 34 + ocg * 16]);
                ull wv2[8];
#pragma unroll
                for (int j = 0; j < 8; ++j) wv2[j] = wrow[j];
#pragma unroll
                for (int k = 0; k < 2; ++k) {
                    int l = pixg + 128 * k;
                    int py = l >> 4, px = l & 15;
                    float ivv = in_s[ic * 324 + (py + ky) * 18 + px + kx];
                    ull iv2 = f2_pack(ivv, ivv);
#pragma unroll
                    for (int j = 0; j < 8; ++j) f2_fma(acc[k][j], iv2, wv2[j]);
                }
            }
        }
    }

    // exchange: buf[px(256)][oc(32)] stride 33
    __syncthreads();
#pragma unroll
    for (int k = 0; k < 2; ++k) {
        int l = pixg + 128 * k;
#pragma unroll
        for (int j = 0; j < 8; ++j) {
            float v0, v1;
            f2_unpack(acc[k][j], v0, v1);
            int oc = ocg * 16 + 2 * j;
            buf[l * 33 + oc]     = v0;
            buf[l * 33 + oc + 1] = v1;
        }
    }
    __syncthreads();

    // epilogue: thread = pixel tid
    {
        int py = tid >> 4, px = tid & 15;
        int gy = ty0 + py, gx = tx0 + px;
        size_t pbase = (size_t)b * 32 * HWs + gy * WW + gx;

        float cn[32];
        float mx = -1e30f;
#pragma unroll
        for (int d = 0; d < 32; ++d) {
            float r = buf[tid * 33 + d] + bias[d];
            float v = 0.5f * (gcost[pbase + (size_t)d * HWs] + r);
            cn[d] = v;
            mx = fmaxf(mx, v);
            out_cost[pbase + (size_t)d * HWs] = v;
        }
        float s = 0.f;
#pragma unroll
        for (int d = 0; d < 32; ++d) { cn[d] = expf(cn[d] - mx); s += cn[d]; }
        float inv = 1.f / s;
#pragma unroll
        for (int d = 0; d < 32; ++d) gnorm[pbase + (size_t)d * HWs] = cn[d] * inv;
    }
}

// =================================================================================
extern "C" void kernel_launch(void* const* d_in, const int* in_sizes, int n_in,
                              void* d_out, int out_size) {
    (void)in_sizes; (void)n_in; (void)out_size;
    const float* t_feat  = (const float*)d_in[0];
    const float* s_feat  = (const float*)d_in[1];
    const float* directs = (const float*)d_in[2];
    const float* qw = (const float*)d_in[3];
    const float* qb = (const float*)d_in[4];
    const float* kw = (const float*)d_in[5];
    const float* kb = (const float*)d_in[6];
    const float* vw = (const float*)d_in[7];
    const float* vb = (const float*)d_in[8];
    const float* p1w = (const float*)d_in[9];
    const float* p1b = (const float*)d_in[10];
    const float* p2w = (const float*)d_in[11];
    const float* p2b = (const float*)d_in[12];
    const float* rw  = (const float*)d_in[13];
    const float* rb  = (const float*)d_in[14];
    const int*   img_w = (const int*)d_in[15];

    float* out_x    = (float*)d_out;
    float* out_cost = out_x + (size_t)BB * CC * HWs;

    float *pq, *pk, *pv, *pagg, *ph1, *pcost, *pnorm;
    cudaGetSymbolAddress((void**)&pq,    g_q);
    cudaGetSymbolAddress((void**)&pk,    g_k);
    cudaGetSymbolAddress((void**)&pv,    g_v);
    cudaGetSymbolAddress((void**)&pagg,  g_agg);
    cudaGetSymbolAddress((void**)&ph1,   g_h1);
    cudaGetSymbolAddress((void**)&pcost, g_cost);
    cudaGetSymbolAddress((void**)&pnorm, g_norm);

    // q/k/v 1x1 convs (GEMMs)
    gemm_qkv_kernel<<<dim3(192, 1, BB), 128>>>(qw, qb, t_feat, pq);
    gemm_qkv_kernel<<<dim3(192, 1, BB), 128>>>(kw, kb, s_feat, pk);
    gemm_qkv_kernel<<<dim3(192, 1, BB), 128>>>(vw, vb, s_feat, pv);

    // fused warp/cost/softmax/agg
    const int attn_smem = (64 * KSTR * 2 + 64 * WW) * (int)sizeof(float);  // 147968
    cudaFuncSetAttribute(attn_kernel, cudaFuncAttributeMaxDynamicSharedMemorySize,
                         attn_smem);
    attn_kernel<<<dim3(HH, BB), WW, attn_smem>>>(pq, pk, pv, directs, img_w,
                                                 pcost, pagg);

    // conv3x3 #1 (+ELU), grid 144 blocks
    conv1_kernel<<<dim3(12, 6, BB), 256>>>(pq, pagg, p1w, p1b, ph1);
    // conv3x3 #2 (+cost merge + softmax)
    conv2_kernel<<<dim3(12, 4, BB), 256>>>(ph1, p2w, p2b, pcost, out_cost, pnorm);

    // final 1x1 (288 -> 256) + ELU
    gemm_final_kernel<<<dim3(192, 4, BB), 128>>>(rw, rb, t_feat, pnorm, out_x);
}

// round 6
// speedup vs baseline: 1.0600x; 1.0600x over previous
#include <cuda_runtime.h>
#include <math.h>

#define BB 2
#define CC 256
#define DD 32
#define HH 64
#define WW 192
#define HWs 12288        // H*W
#define KSTR 193         // k/v row stride in smem (192 + replicated border col)

typedef unsigned long long ull;

// ---------------- packed f32x2 helpers (Blackwell FFMA2) ----------------
__device__ __forceinline__ ull f2_pack(float lo, float hi) {
    ull r;
    asm("mov.b64 %0, {%1, %2};" : "=l"(r) : "f"(lo), "f"(hi));
    return r;
}
__device__ __forceinline__ void f2_unpack(ull v, float& lo, float& hi) {
    asm("mov.b64 {%0, %1}, %2;" : "=f"(lo), "=f"(hi) : "l"(v));
}
__device__ __forceinline__ void f2_fma(ull& d, ull a, ull b) {
    asm("fma.rn.f32x2 %0, %1, %2, %0;" : "+l"(d) : "l"(a), "l"(b));
}

// ---------------- scratch (device globals; no allocation allowed) ----------------
__device__ float g_q   [BB * 64 * HWs];
__device__ float g_k   [BB * 64 * HWs];
__device__ float g_v   [BB * 64 * HWs];
__device__ float g_agg [BB * 64 * HWs];
__device__ float g_h1  [BB * 64 * HWs];
__device__ float g_cost[BB * 32 * HWs];
__device__ float g_norm[BB * 32 * HWs];

// =================================================================================
// Fused q/k/v GEMM:  Y[b][m][n] = sum_k A[m][k] * X[b][k][n] + bias[m]
// M=64, K=256, N=12288.  BM=64, BN=64, BK=16, 128 threads.
// A stored duplicated in smem ([k][2m]) so FFMA2 'a' operands come straight
// from LDS.128 with no packing movs.  blockIdx.y in {0,1,2} selects q/k/v.
// =================================================================================
__global__ void gemm_qkv_kernel(const float* __restrict__ qw, const float* __restrict__ qb,
                                const float* __restrict__ kw, const float* __restrict__ kb,
                                const float* __restrict__ vw, const float* __restrict__ vb,
                                const float* __restrict__ tf, const float* __restrict__ sf,
                                float* __restrict__ yq, float* __restrict__ yk,
                                float* __restrict__ yv) {
    __shared__ __align__(16) float As2[16 * 132];   // [k][2m] duplicated
    __shared__ __align__(16) float Bs[16 * 64];     // [k][n]

    const int which = blockIdx.y;
    const float* A    = (which == 0) ? qw : (which == 1) ? kw : vw;
    const float* bias = (which == 0) ? qb : (which == 1) ? kb : vb;
    const float* X    = (which == 0) ? tf : sf;
    float*       Y    = (which == 0) ? yq : (which == 1) ? yk : yv;

    const int b   = blockIdx.z;
    const int n0  = blockIdx.x * 64;
    const int tid = threadIdx.x;
    const int trow = tid >> 3;      // 0..15
    const int tcol = tid & 7;       // 0..7

    const float* Xb = X + (size_t)b * CC * HWs;

    ull acc[4][4];
#pragma unroll
    for (int i = 0; i < 4; ++i)
#pragma unroll
        for (int j = 0; j < 4; ++j) acc[i][j] = 0ull;

    for (int k0 = 0; k0 < 256; k0 += 16) {
#pragma unroll
        for (int i = 0; i < 8; ++i) {           // A tile: 64x16, store duplicated
            int idx = i * 128 + tid;
            int m = idx >> 4, k = idx & 15;
            float av = A[m * 256 + k0 + k];
            *(ull*)&As2[k * 132 + 2 * m] = f2_pack(av, av);
        }
#pragma unroll
        for (int i = 0; i < 8; ++i) {           // B tile: 16x64
            int idx = i * 128 + tid;
            int k = idx >> 6, n = idx & 63;
            Bs[k * 64 + n] = Xb[(size_t)(k0 + k) * HWs + n0 + n];
        }
        __syncthreads();
#pragma unroll
        for (int kk = 0; kk < 16; ++kk) {
            ulonglong2 a01 = *(const ulonglong2*)&As2[kk * 132 + trow * 8];
            ulonglong2 a23 = *(const ulonglong2*)&As2[kk * 132 + trow * 8 + 4];
            ulonglong2 b01 = *(const ulonglong2*)&Bs[kk * 64 + tcol * 8];
            ulonglong2 b23 = *(const ulonglong2*)&Bs[kk * 64 + tcol * 8 + 4];
            f2_fma(acc[0][0], a01.x, b01.x); f2_fma(acc[0][1], a01.x, b01.y);
            f2_fma(acc[0][2], a01.x, b23.x); f2_fma(acc[0][3], a01.x, b23.y);
            f2_fma(acc[1][0], a01.y, b01.x); f2_fma(acc[1][1], a01.y, b01.y);
            f2_fma(acc[1][2], a01.y, b23.x); f2_fma(acc[1][3], a01.y, b23.y);
            f2_fma(acc[2][0], a23.x, b01.x); f2_fma(acc[2][1], a23.x, b01.y);
            f2_fma(acc[2][2], a23.x, b23.x); f2_fma(acc[2][3], a23.x, b23.y);
            f2_fma(acc[3][0], a23.y, b01.x); f2_fma(acc[3][1], a23.y, b01.y);
            f2_fma(acc[3][2], a23.y, b23.x); f2_fma(acc[3][3], a23.y, b23.y);
        }
        __syncthreads();
    }
#pragma unroll
    for (int i = 0; i < 4; ++i) {
        int m = trow * 4 + i;
        float bi = bias[m];
        float* dst = Y + ((size_t)(b * 64 + m)) * HWs + n0 + tcol * 8;
        float v[8];
#pragma unroll
        for (int j = 0; j < 4; ++j) {
            f2_unpack(acc[i][j], v[2 * j], v[2 * j + 1]);
            v[2 * j] += bi; v[2 * j + 1] += bi;
        }
        *(float4*)&dst[0] = make_float4(v[0], v[1], v[2], v[3]);
        *(float4*)&dst[4] = make_float4(v[4], v[5], v[6], v[7]);
    }
}

// =================================================================================
// Final GEMM: out[b][m][n] = elu( rw[m][:] . concat(t_feat, norm)[b][:][n] + rb[m] )
// M=256, K=288, N=12288.
// =================================================================================
__global__ void gemm_final_kernel(const float* __restrict__ A,      // rw [256][288]
                                  const float* __restrict__ bias,   // rb [256]
                                  const float* __restrict__ tfeat,
                                  const float* __restrict__ nrm,
                                  float* __restrict__ Y) {
    __shared__ __align__(16) float As2[16 * 132];
    __shared__ __align__(16) float Bs[16 * 64];

    const int b   = blockIdx.z;
    const int n0  = blockIdx.x * 64;
    const int m0  = blockIdx.y * 64;
    const int tid = threadIdx.x;
    const int trow = tid >> 3;
    const int tcol = tid & 7;

    ull acc[4][4];
#pragma unroll
    for (int i = 0; i < 4; ++i)
#pragma unroll
        for (int j = 0; j < 4; ++j) acc[i][j] = 0ull;

    for (int k0 = 0; k0 < 288; k0 += 16) {
#pragma unroll
        for (int i = 0; i < 8; ++i) {
            int idx = i * 128 + tid;
            int m = idx >> 4, k = idx & 15;
            float av = A[(m0 + m) * 288 + k0 + k];
            *(ull*)&As2[k * 132 + 2 * m] = f2_pack(av, av);
        }
#pragma unroll
        for (int i = 0; i < 8; ++i) {
            int idx = i * 128 + tid;
            int k = idx >> 6, n = idx & 63;
            int kg = k0 + k;
            const float* src = (kg < 256)
                ? (tfeat + ((size_t)(b * 256 + kg)) * HWs)
                : (nrm + ((size_t)(b * 32 + (kg - 256))) * HWs);
            Bs[k * 64 + n] = src[n0 + n];
        }
        __syncthreads();
#pragma unroll
        for (int kk = 0; kk < 16; ++kk) {
            ulonglong2 a01 = *(const ulonglong2*)&As2[kk * 132 + trow * 8];
            ulonglong2 a23 = *(const ulonglong2*)&As2[kk * 132 + trow * 8 + 4];
            ulonglong2 b01 = *(const ulonglong2*)&Bs[kk * 64 + tcol * 8];
            ulonglong2 b23 = *(const ulonglong2*)&Bs[kk * 64 + tcol * 8 + 4];
            f2_fma(acc[0][0], a01.x, b01.x); f2_fma(acc[0][1], a01.x, b01.y);
            f2_fma(acc[0][2], a01.x, b23.x); f2_fma(acc[0][3], a01.x, b23.y);
            f2_fma(acc[1][0], a01.y, b01.x); f2_fma(acc[1][1], a01.y, b01.y);
            f2_fma(acc[1][2], a01.y, b23.x); f2_fma(acc[1][3], a01.y, b23.y);
            f2_fma(acc[2][0], a23.x, b01.x); f2_fma(acc[2][1], a23.x, b01.y);
            f2_fma(acc[2][2], a23.x, b23.x); f2_fma(acc[2][3], a23.x, b23.y);
            f2_fma(acc[3][0], a23.y, b01.x); f2_fma(acc[3][1], a23.y, b01.y);
            f2_fma(acc[3][2], a23.y, b23.x); f2_fma(acc[3][3], a23.y, b23.y);
        }
        __syncthreads();
    }
#pragma unroll
    for (int i = 0; i < 4; ++i) {
        int m = m0 + trow * 4 + i;
        float bi = bias[m];
        float* dst = Y + ((size_t)(b * 256 + m)) * HWs + n0 + tcol * 8;
        float v[8];
#pragma unroll
        for (int j = 0; j < 4; ++j) {
            f2_unpack(acc[i][j], v[2 * j], v[2 * j + 1]);
        }
#pragma unroll
        for (int j = 0; j < 8; ++j) {
            v[j] += bi;
            v[j] = v[j] > 0.f ? v[j] : (__expf(v[j]) - 1.f);
        }
        *(float4*)&dst[0] = make_float4(v[0], v[1], v[2], v[3]);
        *(float4*)&dst[4] = make_float4(v[4], v[5], v[6], v[7]);
    }
}

// =================================================================================
// Fused warp + cost + softmax + aggregation.
// One block per (h, b). 192 threads, thread = output column w.
// smem: k and v rows only (98.8KB -> 2 blocks/SM). q read from global (prefetch 1).
// =================================================================================
__global__ void attn_kernel(const float* __restrict__ gq,
                            const float* __restrict__ gk,
                            const float* __restrict__ gv,
                            const float* __restrict__ directs,
                            const int*   __restrict__ img_w_i,
                            float* __restrict__ gcost,
                            float* __restrict__ gagg) {
    extern __shared__ float sm[];
    float* ks = sm;                       // 64*193
    float* vs = ks + 64 * KSTR;           // 64*193

    const int h = blockIdx.x;
    const int b = blockIdx.y;
    const int w = threadIdx.x;            // 0..191

    const size_t base = ((size_t)(b * 64)) * HWs + h * WW + w;

    for (int c = 0; c < 64; ++c) {
        size_t off = base + (size_t)c * HWs;
        float kv = gk[off];
        float vv = gv[off];
        ks[c * KSTR + w] = kv;
        vs[c * KSTR + w] = vv;
        if (w == WW - 1) {                // replicate border for x1 = x0+1
            ks[c * KSTR + WW] = kv;
            vs[c * KSTR + WW] = vv;
        }
    }

    // shift step: disps[d]*rel_scale*directs[b]*(W-1), disps[d]=d*0.01
    int iv = img_w_i[0];
    float imw = (iv > 0 && iv < 1000000) ? (float)iv : __int_as_float(iv);
    float ss = directs[b] * (640.0f / imw) * (0.01f * (float)(WW - 1));

    int   ix[DD];
    float fr[DD];
#pragma unroll
    for (int d = 0; d < DD; ++d) {
        float src = fminf(fmaxf((float)w + ss * (float)d, 0.0f), (float)(WW - 1));
        float x0 = floorf(src);
        ix[d] = (int)x0;
        fr[d] = src - x0;
    }
    __syncthreads();

    float cost[DD];
#pragma unroll
    for (int d = 0; d < DD; ++d) cost[d] = 0.f;

    // phase 1: q from global with depth-1 prefetch
    float qn = gq[base];
    for (int c = 0; c < 64; ++c) {
        float qc = qn;
        if (c + 1 < 64) qn = gq[base + (size_t)(c + 1) * HWs];
        const float* kr = ks + c * KSTR;
#pragma unroll
        for (int d = 0; d < DD; ++d) {
            float k0 = kr[ix[d]];
            float k1 = kr[ix[d] + 1];
            cost[d] += qc * (k0 + fr[d] * (k1 - k0));
        }
    }
#pragma unroll
    for (int d = 0; d < DD; ++d) {
        cost[d] *= 0.125f;                // 1/sqrt(64)
        gcost[((size_t)(b * 32 + d)) * HWs + h * WW + w] = cost[d];
    }

    float mx = cost[0];
#pragma unroll
    for (int d = 1; d < DD; ++d) mx = fmaxf(mx, cost[d]);
    float s = 0.f;
#pragma unroll
    for (int d = 0; d < DD; ++d) { cost[d] = __expf(cost[d] - mx); s += cost[d]; }
    float inv = 1.0f / s;
#pragma unroll
    for (int d = 0; d < DD; ++d) cost[d] *= inv;

    for (int c = 0; c < 64; ++c) {
        const float* vr = vs + c * KSTR;
        float acc = 0.f;
#pragma unroll
        for (int d = 0; d < DD; ++d) {
            float v0 = vr[ix[d]];
            float v1 = vr[ix[d] + 1];
            acc += cost[d] * (v0 + fr[d] * (v1 - v0));
        }
        gagg[base + (size_t)c * HWs] = acc;
    }
}

// =================================================================================
// conv3x3 #1: in = concat[q(64), agg(64)] -> 128 ch, out 64 ch, ELU, FFMA2.
// Tile 16w x 11h pixels, grid (12, 6, B) = 144 blocks.
// 256 threads = 4 ocg(16 oc) x 64 pixel-groups (3 px each; 176 used).
// Weight smem stride 68 (16B-aligned rows) -> LDS.128 weight loads.
// =================================================================================
__global__ void conv1_kernel(const float* __restrict__ gq,
                             const float* __restrict__ gagg,
                             const float* __restrict__ wgt,   // [64][128][3][3]
                             const float* __restrict__ bias,  // [64]
                             float* __restrict__ out) {
    __shared__ __align__(16) float in_s[8 * 252];  // 8 ic x 14x18 (row 13 garbage ok)
    __shared__ __align__(16) float w_s[72 * 68];   // [t=ic*9+r9][oc], stride 68

    const int b   = blockIdx.z;
    const int y0  = blockIdx.y * 11;
    const int tx0 = blockIdx.x * 16;
    const int tid = threadIdx.x;
    const int ocg = tid >> 6;            // 0..3
    const int pix = tid & 63;            // 0..63

    int py_[3], px_[3];
    bool val_[3];
#pragma unroll
    for (int k = 0; k < 3; ++k) {
        int l = pix + 64 * k;
        py_[k] = l >> 4;
        px_[k] = l & 15;
        val_[k] = (l < 176);
    }

    ull acc[3][8];
#pragma unroll
    for (int k = 0; k < 3; ++k)
#pragma unroll
        for (int j = 0; j < 8; ++j) acc[k][j] = 0ull;

    for (int c0 = 0; c0 < 128; c0 += 8) {
        __syncthreads();
        // stage input chunk (zero-padded halo), 8 ic x 13 x 18
        for (int idx = tid; idx < 8 * 234; idx += 256) {
            int ic = idx / 234;
            int r  = idx - ic * 234;
            int yy = r / 18, xx = r - yy * 18;
            int gy = y0 + yy - 1, gx = tx0 + xx - 1;
            float v = 0.f;
            if ((unsigned)gy < (unsigned)HH && (unsigned)gx < (unsigned)WW) {
                int icg = c0 + ic;
                const float* src = (icg < 64)
                    ? (gq + ((size_t)(b * 64 + icg)) * HWs)
                    : (gagg + ((size_t)(b * 64 + icg - 64)) * HWs);
                v = src[gy * WW + gx];
            }
            in_s[ic * 252 + r] = v;
        }
        // stage weight chunk
        for (int idx = tid; idx < 64 * 72; idx += 256) {
            int oc = idx / 72, t = idx - oc * 72;
            int ic = t / 9,  r9 = t - ic * 9;
            w_s[t * 68 + oc] = wgt[((oc * 128) + c0 + ic) * 9 + r9];
        }
        __syncthreads();

#pragma unroll 1
        for (int ic = 0; ic < 8; ++ic) {
#pragma unroll
            for (int ky = 0; ky < 3; ++ky)
#pragma unroll
            for (int kx = 0; kx < 3; ++kx) {
                int t = ic * 9 + ky * 3 + kx;
                ulonglong2 w01 = *(const ulonglong2*)&w_s[t * 68 + ocg * 16];
                ulonglong2 w23 = *(const ulonglong2*)&w_s[t * 68 + ocg * 16 + 4];
                ulonglong2 w45 = *(const ulonglong2*)&w_s[t * 68 + ocg * 16 + 8];
                ulonglong2 w67 = *(const ulonglong2*)&w_s[t * 68 + ocg * 16 + 12];
#pragma unroll
                for (int k = 0; k < 3; ++k) {
                    float ivv = in_s[ic * 252 + (py_[k] + ky) * 18 + px_[k] + kx];
                    ull iv2 = f2_pack(ivv, ivv);
                    f2_fma(acc[k][0], iv2, w01.x); f2_fma(acc[k][1], iv2, w01.y);
                    f2_fma(acc[k][2], iv2, w23.x); f2_fma(acc[k][3], iv2, w23.y);
                    f2_fma(acc[k][4], iv2, w45.x); f2_fma(acc[k][5], iv2, w45.y);
                    f2_fma(acc[k][6], iv2, w67.x); f2_fma(acc[k][7], iv2, w67.y);
                }
            }
        }
    }
#pragma unroll
    for (int k = 0; k < 3; ++k) {
        int gy = y0 + py_[k], gx = tx0 + px_[k];
        if (!val_[k] || gy >= HH) continue;
#pragma unroll
        for (int j = 0; j < 8; ++j) {
            int oc = ocg * 16 + 2 * j;
            float v0, v1;
            f2_unpack(acc[k][j], v0, v1);
            v0 += bias[oc];
            v1 += bias[oc + 1];
            v0 = v0 > 0.f ? v0 : (__expf(v0) - 1.f);
            v1 = v1 > 0.f ? v1 : (__expf(v1) - 1.f);
            out[((size_t)(b * 64 + oc)) * HWs + gy * WW + gx]     = v0;
            out[((size_t)(b * 64 + oc + 1)) * HWs + gy * WW + gx] = v1;
        }
    }
}

// =================================================================================
// conv3x3 #2 (64 -> 32) FFMA2, FUSED with: cost = 0.5*(cost_old + res),
// write final cost, softmax over d, write norm.
// Tile 16w x 11h px, grid (12, 6, B) = 144 blocks, 256 threads =
// 2 ocg(16 oc) x 128 px-groups (2 px; 176 used). smem exchange before epilogue.
// =================================================================================
__global__ void conv2_kernel(const float* __restrict__ h1,
                             const float* __restrict__ wgt,   // [32][64][3][3]
                             const float* __restrict__ bias,  // [32]
                             const float* __restrict__ gcost,
                             float* __restrict__ out_cost,
                             float* __restrict__ gnorm) {
    // staging phase uses [in_s | w_s]; exchange phase reuses the whole buffer
    __shared__ __align__(16) float buf[8448];   // >= 8*252 + 72*36 = 4608, and 256*33
    float* in_s = buf;                 // 8*252
    float* w_s  = buf + 8 * 252;       // 72*36 (stride 36 -> 16B-aligned rows)

    const int b   = blockIdx.z;
    const int y0  = blockIdx.y * 11;
    const int tx0 = blockIdx.x * 16;
    const int tid = threadIdx.x;         // 0..255
    const int ocg  = tid >> 7;           // 0..1 (16 oc each)
    const int pixg = tid & 127;          // 0..127

    ull acc[2][8];
#pragma unroll
    for (int k = 0; k < 2; ++k)
#pragma unroll
        for (int j = 0; j < 8; ++j) acc[k][j] = 0ull;

    for (int c0 = 0; c0 < 64; c0 += 8) {
        __syncthreads();
        for (int idx = tid; idx < 8 * 234; idx += 256) {
            int ic = idx / 234;
            int r  = idx - ic * 234;
            int yy = r / 18, xx = r - yy * 18;
            int gy = y0 + yy - 1, gx = tx0 + xx - 1;
            float v = 0.f;
            if ((unsigned)gy < (unsigned)HH && (unsigned)gx < (unsigned)WW) {
                v = h1[((size_t)(b * 64 + c0 + ic)) * HWs + gy * WW + gx];
            }
            in_s[ic * 252 + r] = v;
        }
        for (int idx = tid; idx < 32 * 72; idx += 256) {
            int oc = idx / 72, t = idx - oc * 72;
            int ic = t / 9,  r9 = t - ic * 9;
            w_s[t * 36 + oc] = wgt[((oc * 64) + c0 + ic) * 9 + r9];
        }
        __syncthreads();

#pragma unroll 1
        for (int ic = 0; ic < 8; ++ic) {
#pragma unroll
            for (int ky = 0; ky < 3; ++ky)
#pragma unroll
            for (int kx = 0; kx < 3; ++kx) {
                int t = ic * 9 + ky * 3 + kx;
                ulonglong2 w01 = *(const ulonglong2*)&w_s[t * 36 + ocg * 16];
                ulonglong2 w23 = *(const ulonglong2*)&w_s[t * 36 + ocg * 16 + 4];
                ulonglong2 w45 = *(const ulonglong2*)&w_s[t * 36 + ocg * 16 + 8];
                ulonglong2 w67 = *(const ulonglong2*)&w_s[t * 36 + ocg * 16 + 12];
#pragma unroll
                for (int k = 0; k < 2; ++k) {
                    int l = pixg + 128 * k;
                    int py = l >> 4, px = l & 15;
                    float ivv = in_s[ic * 252 + (py + ky) * 18 + px + kx];
                    ull iv2 = f2_pack(ivv, ivv);
                    f2_fma(acc[k][0], iv2, w01.x); f2_fma(acc[k][1], iv2, w01.y);
                    f2_fma(acc[k][2], iv2, w23.x); f2_fma(acc[k][3], iv2, w23.y);
                    f2_fma(acc[k][4], iv2, w45.x); f2_fma(acc[k][5], iv2, w45.y);
                    f2_fma(acc[k][6], iv2, w67.x); f2_fma(acc[k][7], iv2, w67.y);
                }
            }
        }
    }

    // exchange: buf[px(256)][oc(32)] stride 33
    __syncthreads();
#pragma unroll
    for (int k = 0; k < 2; ++k) {
        int l = pixg + 128 * k;
#pragma unroll
        for (int j = 0; j < 8; ++j) {
            float v0, v1;
            f2_unpack(acc[k][j], v0, v1);
            int oc = ocg * 16 + 2 * j;
            buf[l * 33 + oc]     = v0;
            buf[l * 33 + oc + 1] = v1;
        }
    }
    __syncthreads();

    // epilogue: thread = pixel tid (176 valid)
    if (tid < 176) {
        int py = tid >> 4, px = tid & 15;
        int gy = y0 + py, gx = tx0 + px;
        if (gy < HH) {
            size_t pbase = (size_t)b * 32 * HWs + gy * WW + gx;

            float cn[32];
            float mx = -1e30f;
#pragma unroll
            for (int d = 0; d < 32; ++d) {
                float r = buf[tid * 33 + d] + bias[d];
                float v = 0.5f * (gcost[pbase + (size_t)d * HWs] + r);
                cn[d] = v;
                mx = fmaxf(mx, v);
                out_cost[pbase + (size_t)d * HWs] = v;
            }
            float s = 0.f;
#pragma unroll
            for (int d = 0; d < 32; ++d) { cn[d] = __expf(cn[d] - mx); s += cn[d]; }
            float inv = 1.f / s;
#pragma unroll
            for (int d = 0; d < 32; ++d) gnorm[pbase + (size_t)d * HWs] = cn[d] * inv;
        }
    }
}

// =================================================================================
extern "C" void kernel_launch(void* const* d_in, const int* in_sizes, int n_in,
                              void* d_out, int out_size) {
    (void)in_sizes; (void)n_in; (void)out_size;
    const float* t_feat  = (const float*)d_in[0];
    const float* s_feat  = (const float*)d_in[1];
    const float* directs = (const float*)d_in[2];
    const float* qw = (const float*)d_in[3];
    const float* qb = (const float*)d_in[4];
    const float* kw = (const float*)d_in[5];
    const float* kb = (const float*)d_in[6];
    const float* vw = (const float*)d_in[7];
    const float* vb = (const float*)d_in[8];
    const float* p1w = (const float*)d_in[9];
    const float* p1b = (const float*)d_in[10];
    const float* p2w = (const float*)d_in[11];
    const float* p2b = (const float*)d_in[12];
    const float* rw  = (const float*)d_in[13];
    const float* rb  = (const float*)d_in[14];
    const int*   img_w = (const int*)d_in[15];

    float* out_x    = (float*)d_out;
    float* out_cost = out_x + (size_t)BB * CC * HWs;

    float *pq, *pk, *pv, *pagg, *ph1, *pcost, *pnorm;
    cudaGetSymbolAddress((void**)&pq,    g_q);
    cudaGetSymbolAddress((void**)&pk,    g_k);
    cudaGetSymbolAddress((void**)&pv,    g_v);
    cudaGetSymbolAddress((void**)&pagg,  g_agg);
    cudaGetSymbolAddress((void**)&ph1,   g_h1);
    cudaGetSymbolAddress((void**)&pcost, g_cost);
    cudaGetSymbolAddress((void**)&pnorm, g_norm);

    // fused q/k/v 1x1 convs (one launch, blockIdx.y selects q/k/v)
    gemm_qkv_kernel<<<dim3(192, 3, BB), 128>>>(qw, qb, kw, kb, vw, vb,
                                               t_feat, s_feat, pq, pk, pv);

    // fused warp/cost/softmax/agg (k/v smem only -> 2 blocks/SM)
    const int attn_smem = (64 * KSTR * 2) * (int)sizeof(float);  // 98816
    cudaFuncSetAttribute(attn_kernel, cudaFuncAttributeMaxDynamicSharedMemorySize,
                         attn_smem);
    attn_kernel<<<dim3(HH, BB), WW, attn_smem>>>(pq, pk, pv, directs, img_w,
                                                 pcost, pagg);

    // conv3x3 #1 (+ELU), 144 blocks
    conv1_kernel<<<dim3(12, 6, BB), 256>>>(pq, pagg, p1w, p1b, ph1);
    // conv3x3 #2 (+cost merge + softmax), 144 blocks
    conv2_kernel<<<dim3(12, 6, BB), 256>>>(ph1, p2w, p2b, pcost, out_cost, pnorm);

    // final 1x1 (288 -> 256) + ELU
    gemm_final_kernel<<<dim3(192, 4, BB), 128>>>(rw, rb, t_feat, pnorm, out_x);
}

// round 8
// speedup vs baseline: 1.1307x; 1.0666x over previous
#include <cuda_runtime.h>
#include <math.h>

#define BB 2
#define CC 256
#define DD 32
#define HH 64
#define WW 192
#define HWs 12288        // H*W
#define KSTR 193         // k/v row stride in smem (192 + replicated border col)

typedef unsigned long long ull;

// ---------------- packed f32x2 helpers (Blackwell FFMA2) ----------------
__device__ __forceinline__ ull f2_pack(float lo, float hi) {
    ull r;
    asm("mov.b64 %0, {%1, %2};" : "=l"(r) : "f"(lo), "f"(hi));
    return r;
}
__device__ __forceinline__ void f2_unpack(ull v, float& lo, float& hi) {
    asm("mov.b64 {%0, %1}, %2;" : "=f"(lo), "=f"(hi) : "l"(v));
}
__device__ __forceinline__ void f2_fma(ull& d, ull a, ull b) {
    asm("fma.rn.f32x2 %0, %1, %2, %0;" : "+l"(d) : "l"(a), "l"(b));
}

// ---------------- scratch (device globals; no allocation allowed) ----------------
__device__ float g_q   [BB * 64 * HWs];
__device__ float g_k   [BB * 64 * HWs];
__device__ float g_v   [BB * 64 * HWs];
__device__ float g_agg [BB * 64 * HWs];
__device__ float g_h1a [BB * 64 * HWs];   // conv1 partial (ic 0..63  = q half)
__device__ float g_h1b [BB * 64 * HWs];   // conv1 partial (ic 64..127 = agg half)
__device__ float g_c2a [BB * 32 * HWs];   // conv2 partial (ic 0..31)
__device__ float g_c2b [BB * 32 * HWs];   // conv2 partial (ic 32..63)
__device__ float g_cost[BB * 32 * HWs];
__device__ float g_norm[BB * 32 * HWs];

// =================================================================================
// Fused q/k/v GEMM:  Y[b][m][n] = sum_k A[m][k] * X[b][k][n] + bias[m]
// M=64, K=256, N=12288.  BM=64, BN=64, BK=16, 128 threads.
// A stored duplicated in smem ([k][2m]) -> FFMA2 'a' operands via LDS.128.
// =================================================================================
__global__ void gemm_qkv_kernel(const float* __restrict__ qw, const float* __restrict__ qb,
                                const float* __restrict__ kw, const float* __restrict__ kb,
                                const float* __restrict__ vw, const float* __restrict__ vb,
                                const float* __restrict__ tf, const float* __restrict__ sf,
                                float* __restrict__ yq, float* __restrict__ yk,
                                float* __restrict__ yv) {
    __shared__ __align__(16) float As2[16 * 132];   // [k][2m] duplicated
    __shared__ __align__(16) float Bs[16 * 64];     // [k][n]

    const int which = blockIdx.y;
    const float* A    = (which == 0) ? qw : (which == 1) ? kw : vw;
    const float* bias = (which == 0) ? qb : (which == 1) ? kb : vb;
    const float* X    = (which == 0) ? tf : sf;
    float*       Y    = (which == 0) ? yq : (which == 1) ? yk : yv;

    const int b   = blockIdx.z;
    const int n0  = blockIdx.x * 64;
    const int tid = threadIdx.x;
    const int trow = tid >> 3;      // 0..15
    const int tcol = tid & 7;       // 0..7

    const float* Xb = X + (size_t)b * CC * HWs;

    ull acc[4][4];
#pragma unroll
    for (int i = 0; i < 4; ++i)
#pragma unroll
        for (int j = 0; j < 4; ++j) acc[i][j] = 0ull;

    for (int k0 = 0; k0 < 256; k0 += 16) {
#pragma unroll
        for (int i = 0; i < 8; ++i) {           // A tile: 64x16, store duplicated
            int idx = i * 128 + tid;
            int m = idx >> 4, k = idx & 15;
            float av = A[m * 256 + k0 + k];
            *(ull*)&As2[k * 132 + 2 * m] = f2_pack(av, av);
        }
#pragma unroll
        for (int i = 0; i < 8; ++i) {           // B tile: 16x64
            int idx = i * 128 + tid;
            int k = idx >> 6, n = idx & 63;
            Bs[k * 64 + n] = Xb[(size_t)(k0 + k) * HWs + n0 + n];
        }
        __syncthreads();
#pragma unroll
        for (int kk = 0; kk < 16; ++kk) {
            ulonglong2 a01 = *(const ulonglong2*)&As2[kk * 132 + trow * 8];
            ulonglong2 a23 = *(const ulonglong2*)&As2[kk * 132 + trow * 8 + 4];
            ulonglong2 b01 = *(const ulonglong2*)&Bs[kk * 64 + tcol * 8];
            ulonglong2 b23 = *(const ulonglong2*)&Bs[kk * 64 + tcol * 8 + 4];
            f2_fma(acc[0][0], a01.x, b01.x); f2_fma(acc[0][1], a01.x, b01.y);
            f2_fma(acc[0][2], a01.x, b23.x); f2_fma(acc[0][3], a01.x, b23.y);
            f2_fma(acc[1][0], a01.y, b01.x); f2_fma(acc[1][1], a01.y, b01.y);
            f2_fma(acc[1][2], a01.y, b23.x); f2_fma(acc[1][3], a01.y, b23.y);
            f2_fma(acc[2][0], a23.x, b01.x); f2_fma(acc[2][1], a23.x, b01.y);
            f2_fma(acc[2][2], a23.x, b23.x); f2_fma(acc[2][3], a23.x, b23.y);
            f2_fma(acc[3][0], a23.y, b01.x); f2_fma(acc[3][1], a23.y, b01.y);
            f2_fma(acc[3][2], a23.y, b23.x); f2_fma(acc[3][3], a23.y, b23.y);
        }
        __syncthreads();
    }
#pragma unroll
    for (int i = 0; i < 4; ++i) {
        int m = trow * 4 + i;
        float bi = bias[m];
        float* dst = Y + ((size_t)(b * 64 + m)) * HWs + n0 + tcol * 8;
        float v[8];
#pragma unroll
        for (int j = 0; j < 4; ++j) {
            f2_unpack(acc[i][j], v[2 * j], v[2 * j + 1]);
            v[2 * j] += bi; v[2 * j + 1] += bi;
        }
        *(float4*)&dst[0] = make_float4(v[0], v[1], v[2], v[3]);
        *(float4*)&dst[4] = make_float4(v[4], v[5], v[6], v[7]);
    }
}

// =================================================================================
// Final GEMM: out[b][m][n] = elu( rw[m][:] . concat(t_feat, norm)[b][:][n] + rb[m] )
// M=256, K=288, N=12288.
// =================================================================================
__global__ void gemm_final_kernel(const float* __restrict__ A,      // rw [256][288]
                                  const float* __restrict__ bias,   // rb [256]
                                  const float* __restrict__ tfeat,
                                  const float* __restrict__ nrm,
                                  float* __restrict__ Y) {
    __shared__ __align__(16) float As2[16 * 132];
    __shared__ __align__(16) float Bs[16 * 64];

    const int b   = blockIdx.z;
    const int n0  = blockIdx.x * 64;
    const int m0  = blockIdx.y * 64;
    const int tid = threadIdx.x;
    const int trow = tid >> 3;
    const int tcol = tid & 7;

    ull acc[4][4];
#pragma unroll
    for (int i = 0; i < 4; ++i)
#pragma unroll
        for (int j = 0; j < 4; ++j) acc[i][j] = 0ull;

    for (int k0 = 0; k0 < 288; k0 += 16) {
#pragma unroll
        for (int i = 0; i < 8; ++i) {
            int idx = i * 128 + tid;
            int m = idx >> 4, k = idx & 15;
            float av = A[(m0 + m) * 288 + k0 + k];
            *(ull*)&As2[k * 132 + 2 * m] = f2_pack(av, av);
        }
#pragma unroll
        for (int i = 0; i < 8; ++i) {
            int idx = i * 128 + tid;
            int k = idx >> 6, n = idx & 63;
            int kg = k0 + k;
            const float* src = (kg < 256)
                ? (tfeat + ((size_t)(b * 256 + kg)) * HWs)
                : (nrm + ((size_t)(b * 32 + (kg - 256))) * HWs);
            Bs[k * 64 + n] = src[n0 + n];
        }
        __syncthreads();
#pragma unroll
        for (int kk = 0; kk < 16; ++kk) {
            ulonglong2 a01 = *(const ulonglong2*)&As2[kk * 132 + trow * 8];
            ulonglong2 a23 = *(const ulonglong2*)&As2[kk * 132 + trow * 8 + 4];
            ulonglong2 b01 = *(const ulonglong2*)&Bs[kk * 64 + tcol * 8];
            ulonglong2 b23 = *(const ulonglong2*)&Bs[kk * 64 + tcol * 8 + 4];
            f2_fma(acc[0][0], a01.x, b01.x); f2_fma(acc[0][1], a01.x, b01.y);
            f2_fma(acc[0][2], a01.x, b23.x); f2_fma(acc[0][3], a01.x, b23.y);
            f2_fma(acc[1][0], a01.y, b01.x); f2_fma(acc[1][1], a01.y, b01.y);
            f2_fma(acc[1][2], a01.y, b23.x); f2_fma(acc[1][3], a01.y, b23.y);
            f2_fma(acc[2][0], a23.x, b01.x); f2_fma(acc[2][1], a23.x, b01.y);
            f2_fma(acc[2][2], a23.x, b23.x); f2_fma(acc[2][3], a23.x, b23.y);
            f2_fma(acc[3][0], a23.y, b01.x); f2_fma(acc[3][1], a23.y, b01.y);
            f2_fma(acc[3][2], a23.y, b23.x); f2_fma(acc[3][3], a23.y, b23.y);
        }
        __syncthreads();
    }
#pragma unroll
    for (int i = 0; i < 4; ++i) {
        int m = m0 + trow * 4 + i;
        float bi = bias[m];
        float* dst = Y + ((size_t)(b * 256 + m)) * HWs + n0 + tcol * 8;
        float v[8];
#pragma unroll
        for (int j = 0; j < 4; ++j) {
            f2_unpack(acc[i][j], v[2 * j], v[2 * j + 1]);
        }
#pragma unroll
        for (int j = 0; j < 8; ++j) {
            v[j] += bi;
            v[j] = v[j] > 0.f ? v[j] : (__expf(v[j]) - 1.f);
        }
        *(float4*)&dst[0] = make_float4(v[0], v[1], v[2], v[3]);
        *(float4*)&dst[4] = make_float4(v[4], v[5], v[6], v[7]);
    }
}

// =================================================================================
// Fused warp + cost + softmax + aggregation.  (unchanged from R2-best shape)
// =================================================================================
__global__ void attn_kernel(const float* __restrict__ gq,
                            const float* __restrict__ gk,
                            const float* __restrict__ gv,
                            const float* __restrict__ directs,
                            const int*   __restrict__ img_w_i,
                            float* __restrict__ gcost,
                            float* __restrict__ gagg) {
    extern __shared__ float sm[];
    float* ks = sm;                       // 64*193
    float* vs = ks + 64 * KSTR;           // 64*193

    const int h = blockIdx.x;
    const int b = blockIdx.y;
    const int w = threadIdx.x;            // 0..191

    const size_t base = ((size_t)(b * 64)) * HWs + h * WW + w;

    for (int c = 0; c < 64; ++c) {
        size_t off = base + (size_t)c * HWs;
        float kv = gk[off];
        float vv = gv[off];
        ks[c * KSTR + w] = kv;
        vs[c * KSTR + w] = vv;
        if (w == WW - 1) {                // replicate border for x1 = x0+1
            ks[c * KSTR + WW] = kv;
            vs[c * KSTR + WW] = vv;
        }
    }

    int iv = img_w_i[0];
    float imw = (iv > 0 && iv < 1000000) ? (float)iv : __int_as_float(iv);
    float ss = directs[b] * (640.0f / imw) * (0.01f * (float)(WW - 1));

    int   ix[DD];
    float fr[DD];
#pragma unroll
    for (int d = 0; d < DD; ++d) {
        float src = fminf(fmaxf((float)w + ss * (float)d, 0.0f), (float)(WW - 1));
        float x0 = floorf(src);
        ix[d] = (int)x0;
        fr[d] = src - x0;
    }
    __syncthreads();

    float cost[DD];
#pragma unroll
    for (int d = 0; d < DD; ++d) cost[d] = 0.f;

    float qn = gq[base];
    for (int c = 0; c < 64; ++c) {
        float qc = qn;
        if (c + 1 < 64) qn = gq[base + (size_t)(c + 1) * HWs];
        const float* kr = ks + c * KSTR;
#pragma unroll
        for (int d = 0; d < DD; ++d) {
            float k0 = kr[ix[d]];
            float k1 = kr[ix[d] + 1];
            cost[d] += qc * (k0 + fr[d] * (k1 - k0));
        }
    }
#pragma unroll
    for (int d = 0; d < DD; ++d) {
        cost[d] *= 0.125f;                // 1/sqrt(64)
        gcost[((size_t)(b * 32 + d)) * HWs + h * WW + w] = cost[d];
    }

    float mx = cost[0];
#pragma unroll
    for (int d = 1; d < DD; ++d) mx = fmaxf(mx, cost[d]);
    float s = 0.f;
#pragma unroll
    for (int d = 0; d < DD; ++d) { cost[d] = __expf(cost[d] - mx); s += cost[d]; }
    float inv = 1.0f / s;
#pragma unroll
    for (int d = 0; d < DD; ++d) cost[d] *= inv;

    for (int c = 0; c < 64; ++c) {
        const float* vr = vs + c * KSTR;
        float acc = 0.f;
#pragma unroll
        for (int d = 0; d < DD; ++d) {
            float v0 = vr[ix[d]];
            float v1 = vr[ix[d] + 1];
            acc += cost[d] * (v0 + fr[d] * (v1 - v0));
        }
        gagg[base + (size_t)c * HWs] = acc;
    }
}

// =================================================================================
// conv3x3 #1 SPLIT-K: each block sums over 64 of the 128 input channels.
// ks=0 -> q channels (ic 0..63), ks=1 -> agg channels (ic 64..127).
// Writes RAW partial sums (no bias/ELU) to outa/outb; combine fused into conv2.
// Tile 16w x 11h, grid (12, 6, BB*2) = 288 blocks -> ~2 CTAs/SM.
// =================================================================================
__global__ void conv1_kernel(const float* __restrict__ gq,
                             const float* __restrict__ gagg,
                             const float* __restrict__ wgt,   // [64][128][3][3]
                             float* __restrict__ outa,
                             float* __restrict__ outb) {
    __shared__ __align__(16) float in_s[8 * 252];  // 8 ic x 14x18 (row 13 scratch)
    __shared__ __align__(16) float w_s[72 * 68];   // [t=ic*9+r9][oc], stride 68

    const int bz  = blockIdx.z;
    const int b   = bz >> 1;
    const int ks  = bz & 1;
    const int y0  = blockIdx.y * 11;
    const int tx0 = blockIdx.x * 16;
    const int tid = threadIdx.x;
    const int ocg = tid >> 6;            // 0..3
    const int pix = tid & 63;            // 0..63

    const float* src_base = (ks == 0) ? gq : gagg;   // both are [b][64][HWs]
    float* out = (ks == 0) ? outa : outb;

    int py_[3], px_[3];
    bool val_[3];
#pragma unroll
    for (int k = 0; k < 3; ++k) {
        int l = pix + 64 * k;
        py_[k] = l >> 4;
        px_[k] = l & 15;
        val_[k] = (l < 176);
    }

    ull acc[3][8];
#pragma unroll
    for (int k = 0; k < 3; ++k)
#pragma unroll
        for (int j = 0; j < 8; ++j) acc[k][j] = 0ull;

    for (int c0 = 0; c0 < 64; c0 += 8) {
        __syncthreads();
        // stage input chunk (zero-padded halo), 8 ic x 13 x 18
        for (int idx = tid; idx < 8 * 234; idx += 256) {
            int ic = idx / 234;
            int r  = idx - ic * 234;
            int yy = r / 18, xx = r - yy * 18;
            int gy = y0 + yy - 1, gx = tx0 + xx - 1;
            float v = 0.f;
            if ((unsigned)gy < (unsigned)HH && (unsigned)gx < (unsigned)WW) {
                v = src_base[((size_t)(b * 64 + c0 + ic)) * HWs + gy * WW + gx];
            }
            in_s[ic * 252 + r] = v;
        }
        // stage weight chunk (global ic = ks*64 + c0 + ic)
        for (int idx = tid; idx < 64 * 72; idx += 256) {
            int oc = idx / 72, t = idx - oc * 72;
            int ic = t / 9,  r9 = t - ic * 9;
            w_s[t * 68 + oc] = wgt[((oc * 128) + ks * 64 + c0 + ic) * 9 + r9];
        }
        __syncthreads();

#pragma unroll 1
        for (int ic = 0; ic < 8; ++ic) {
#pragma unroll
            for (int ky = 0; ky < 3; ++ky)
#pragma unroll
            for (int kx = 0; kx < 3; ++kx) {
                int t = ic * 9 + ky * 3 + kx;
                ulonglong2 w01 = *(const ulonglong2*)&w_s[t * 68 + ocg * 16];
                ulonglong2 w23 = *(const ulonglong2*)&w_s[t * 68 + ocg * 16 + 4];
                ulonglong2 w45 = *(const ulonglong2*)&w_s[t * 68 + ocg * 16 + 8];
                ulonglong2 w67 = *(const ulonglong2*)&w_s[t * 68 + ocg * 16 + 12];
#pragma unroll
                for (int k = 0; k < 3; ++k) {
                    float ivv = in_s[ic * 252 + (py_[k] + ky) * 18 + px_[k] + kx];
                    ull iv2 = f2_pack(ivv, ivv);
                    f2_fma(acc[k][0], iv2, w01.x); f2_fma(acc[k][1], iv2, w01.y);
                    f2_fma(acc[k][2], iv2, w23.x); f2_fma(acc[k][3], iv2, w23.y);
                    f2_fma(acc[k][4], iv2, w45.x); f2_fma(acc[k][5], iv2, w45.y);
                    f2_fma(acc[k][6], iv2, w67.x); f2_fma(acc[k][7], iv2, w67.y);
                }
            }
        }
    }
#pragma unroll
    for (int k = 0; k < 3; ++k) {
        int gy = y0 + py_[k], gx = tx0 + px_[k];
        if (!val_[k] || gy >= HH) continue;
#pragma unroll
        for (int j = 0; j < 8; ++j) {
            int oc = ocg * 16 + 2 * j;
            float v0, v1;
            f2_unpack(acc[k][j], v0, v1);
            out[((size_t)(b * 64 + oc)) * HWs + gy * WW + gx]     = v0;
            out[((size_t)(b * 64 + oc + 1)) * HWs + gy * WW + gx] = v1;
        }
    }
}

// =================================================================================
// conv3x3 #2 SPLIT-K (64 -> 32): block handles 32 of the 64 ic.
// Staging fuses conv1 combine: h1 = elu(p0 + p1 + bias1) (0 for OOB halo).
// Writes pre-bias partial sums to c2a/c2b; epilogue moved to combine_kernel.
// Tile 16w x 11h, grid (12, 6, BB*2) = 288 blocks, 256 thr = 2 ocg x 128 pxg(2px).
// =================================================================================
__global__ void conv2_kernel(const float* __restrict__ p0,     // conv1 partial a
                             const float* __restrict__ p1,     // conv1 partial b
                             const float* __restrict__ bias1,  // p1b [64]
                             const float* __restrict__ wgt,    // [32][64][3][3]
                             float* __restrict__ c2a,
                             float* __restrict__ c2b) {
    __shared__ __align__(16) float buf[8448];   // in_s 8*252 | w_s 72*36; exch 256*33
    float* in_s = buf;                 // 8*252
    float* w_s  = buf + 8 * 252;       // 72*36

    const int bz  = blockIdx.z;
    const int b   = bz >> 1;
    const int ks  = bz & 1;
    const int y0  = blockIdx.y * 11;
    const int tx0 = blockIdx.x * 16;
    const int tid = threadIdx.x;         // 0..255
    const int ocg  = tid >> 7;           // 0..1 (16 oc each)
    const int pixg = tid & 127;          // 0..127

    float* outp = (ks == 0) ? c2a : c2b;

    ull acc[2][8];
#pragma unroll
    for (int k = 0; k < 2; ++k)
#pragma unroll
        for (int j = 0; j < 8; ++j) acc[k][j] = 0ull;

    for (int c0 = 0; c0 < 32; c0 += 8) {
        __syncthreads();
        for (int idx = tid; idx < 8 * 234; idx += 256) {
            int ic = idx / 234;
            int r  = idx - ic * 234;
            int yy = r / 18, xx = r - yy * 18;
            int gy = y0 + yy - 1, gx = tx0 + xx - 1;
            float v = 0.f;
            if ((unsigned)gy < (unsigned)HH && (unsigned)gx < (unsigned)WW) {
                int icg = ks * 32 + c0 + ic;
                size_t off = ((size_t)(b * 64 + icg)) * HWs + gy * WW + gx;
                float t = p0[off] + p1[off] + bias1[icg];
                v = t > 0.f ? t : (__expf(t) - 1.f);
            }
            in_s[ic * 252 + r] = v;
        }
        for (int idx = tid; idx < 32 * 72; idx += 256) {
            int oc = idx / 72, t = idx - oc * 72;
            int ic = t / 9,  r9 = t - ic * 9;
            w_s[t * 36 + oc] = wgt[((oc * 64) + ks * 32 + c0 + ic) * 9 + r9];
        }
        __syncthreads();

#pragma unroll 1
        for (int ic = 0; ic < 8; ++ic) {
#pragma unroll
            for (int ky = 0; ky < 3; ++ky)
#pragma unroll
            for (int kx = 0; kx < 3; ++kx) {
                int t = ic * 9 + ky * 3 + kx;
                ulonglong2 w01 = *(const ulonglong2*)&w_s[t * 36 + ocg * 16];
                ulonglong2 w23 = *(const ulonglong2*)&w_s[t * 36 + ocg * 16 + 4];
                ulonglong2 w45 = *(const ulonglong2*)&w_s[t * 36 + ocg * 16 + 8];
                ulonglong2 w67 = *(const ulonglong2*)&w_s[t * 36 + ocg * 16 + 12];
#pragma unroll
                for (int k = 0; k < 2; ++k) {
                    int l = pixg + 128 * k;
                    int py = l >> 4, px = l & 15;
                    float ivv = in_s[ic * 252 + (py + ky) * 18 + px + kx];
                    ull iv2 = f2_pack(ivv, ivv);
                    f2_fma(acc[k][0], iv2, w01.x); f2_fma(acc[k][1], iv2, w01.y);
                    f2_fma(acc[k][2], iv2, w23.x); f2_fma(acc[k][3], iv2, w23.y);
                    f2_fma(acc[k][4], iv2, w45.x); f2_fma(acc[k][5], iv2, w45.y);
                    f2_fma(acc[k][6], iv2, w67.x); f2_fma(acc[k][7], iv2, w67.y);
                }
            }
        }
    }

    // exchange so each pixel's 32 oc are contiguous per thread -> coalesced STG
    __syncthreads();
#pragma unroll
    for (int k = 0; k < 2; ++k) {
        int l = pixg + 128 * k;
#pragma unroll
        for (int j = 0; j < 8; ++j) {
            float v0, v1;
            f2_unpack(acc[k][j], v0, v1);
            int oc = ocg * 16 + 2 * j;
            buf[l * 33 + oc]     = v0;
            buf[l * 33 + oc + 1] = v1;
        }
    }
    __syncthreads();

    if (tid < 176) {
        int py = tid >> 4, px = tid & 15;
        int gy = y0 + py, gx = tx0 + px;
        if (gy < HH) {
            size_t pbase = (size_t)b * 32 * HWs + gy * WW + gx;
#pragma unroll
            for (int d = 0; d < 32; ++d)
                outp[pbase + (size_t)d * HWs] = buf[tid * 33 + d];
        }
    }
}

// =================================================================================
// Combine: res = c2a + c2b + bias2; cost = 0.5*(cost_attn + res); write cost;
// softmax over d -> norm.  One thread per pixel. grid (48, BB) x 256.
// =================================================================================
__global__ void combine_kernel(const float* __restrict__ c2a,
                               const float* __restrict__ c2b,
                               const float* __restrict__ bias2,  // p2b [32]
                               const float* __restrict__ gcost,
                               float* __restrict__ out_cost,
                               float* __restrict__ gnorm) {
    const int b = blockIdx.y;
    const int p = blockIdx.x * 256 + threadIdx.x;    // 0..12287
    size_t base = (size_t)b * 32 * HWs + p;

    float cn[32];
    float mx = -1e30f;
#pragma unroll
    for (int d = 0; d < 32; ++d) {
        size_t off = base + (size_t)d * HWs;
        float r = c2a[off] + c2b[off] + bias2[d];
        float v = 0.5f * (gcost[off] + r);
        cn[d] = v;
        mx = fmaxf(mx, v);
        out_cost[off] = v;
    }
    float s = 0.f;
#pragma unroll
    for (int d = 0; d < 32; ++d) { cn[d] = __expf(cn[d] - mx); s += cn[d]; }
    float inv = 1.f / s;
#pragma unroll
    for (int d = 0; d < 32; ++d) gnorm[base + (size_t)d * HWs] = cn[d] * inv;
}

// =================================================================================
extern "C" void kernel_launch(void* const* d_in, const int* in_sizes, int n_in,
                              void* d_out, int out_size) {
    (void)in_sizes; (void)n_in; (void)out_size;
    const float* t_feat  = (const float*)d_in[0];
    const float* s_feat  = (const float*)d_in[1];
    const float* directs = (const float*)d_in[2];
    const float* qw = (const float*)d_in[3];
    const float* qb = (const float*)d_in[4];
    const float* kw = (const float*)d_in[5];
    const float* kb = (const float*)d_in[6];
    const float* vw = (const float*)d_in[7];
    const float* vb = (const float*)d_in[8];
    const float* p1w = (const float*)d_in[9];
    const float* p1b = (const float*)d_in[10];
    const float* p2w = (const float*)d_in[11];
    const float* p2b = (const float*)d_in[12];
    const float* rw  = (const float*)d_in[13];
    const float* rb  = (const float*)d_in[14];
    const int*   img_w = (const int*)d_in[15];

    float* out_x    = (float*)d_out;
    float* out_cost = out_x + (size_t)BB * CC * HWs;

    float *pq, *pk, *pv, *pagg, *ph1a, *ph1b, *pc2a, *pc2b, *pcost, *pnorm;
    cudaGetSymbolAddress((void**)&pq,    g_q);
    cudaGetSymbolAddress((void**)&pk,    g_k);
    cudaGetSymbolAddress((void**)&pv,    g_v);
    cudaGetSymbolAddress((void**)&pagg,  g_agg);
    cudaGetSymbolAddress((void**)&ph1a,  g_h1a);
    cudaGetSymbolAddress((void**)&ph1b,  g_h1b);
    cudaGetSymbolAddress((void**)&pc2a,  g_c2a);
    cudaGetSymbolAddress((void**)&pc2b,  g_c2b);
    cudaGetSymbolAddress((void**)&pcost, g_cost);
    cudaGetSymbolAddress((void**)&pnorm, g_norm);

    // fused q/k/v 1x1 convs
    gemm_qkv_kernel<<<dim3(192, 3, BB), 128>>>(qw, qb, kw, kb, vw, vb,
                                               t_feat, s_feat, pq, pk, pv);

    // fused warp/cost/softmax/agg (2 blocks/SM)
    const int attn_smem = (64 * KSTR * 2) * (int)sizeof(float);  // 98816
    cudaFuncSetAttribute(attn_kernel, cudaFuncAttributeMaxDynamicSharedMemorySize,
                         attn_smem);
    attn_kernel<<<dim3(HH, BB), WW, attn_smem>>>(pq, pk, pv, directs, img_w,
                                                 pcost, pagg);

    // conv3x3 #1 split-K (raw partials), 288 blocks
    conv1_kernel<<<dim3(12, 6, BB * 2), 256>>>(pq, pagg, p1w, ph1a, ph1b);
    // conv3x3 #2 split-K (staging fuses conv1 bias+ELU), 288 blocks
    conv2_kernel<<<dim3(12, 6, BB * 2), 256>>>(ph1a, ph1b, p1b, p2w, pc2a, pc2b);
    // combine: cost merge + softmax
    combine_kernel<<<dim3(48, BB), 256>>>(pc2a, pc2b, p2b, pcost, out_cost, pnorm);

    // final 1x1 (288 -> 256) + ELU
    gemm_final_kernel<<<dim3(192, 4, BB), 128>>>(rw, rb, t_feat, pnorm, out_x);
}

// round 11
// speedup vs baseline: 1.1964x; 1.0581x over previous
#include <cuda_runtime.h>
#include <math.h>

#define BB 2
#define CC 256
#define DD 32
#define HH 64
#define WW 192
#define HWs 12288        // H*W
#define KSTR 193         // k/v row stride in smem (192 + replicated border col)

typedef unsigned long long ull;

// ---------------- packed f32x2 helpers (Blackwell FFMA2) ----------------
__device__ __forceinline__ ull f2_pack(float lo, float hi) {
    ull r;
    asm("mov.b64 %0, {%1, %2};" : "=l"(r) : "f"(lo), "f"(hi));
    return r;
}
__device__ __forceinline__ void f2_unpack(ull v, float& lo, float& hi) {
    asm("mov.b64 {%0, %1}, %2;" : "=f"(lo), "=f"(hi) : "l"(v));
}
__device__ __forceinline__ void f2_fma(ull& d, ull a, ull b) {
    asm("fma.rn.f32x2 %0, %1, %2, %0;" : "+l"(d) : "l"(a), "l"(b));
}

// ---------------- scratch (device globals; no allocation allowed) ----------------
__device__ float g_q   [BB * 64 * HWs];
__device__ float g_k   [BB * 64 * HWs];
__device__ float g_v   [BB * 64 * HWs];
__device__ float g_agg [BB * 64 * HWs];
__device__ float g_h1a [BB * 64 * HWs];   // conv1 partial (q half)
__device__ float g_h1b [BB * 64 * HWs];   // conv1 partial (agg half)
__device__ float g_c2a [BB * 32 * HWs];   // conv2 partial (ic 0..31)
__device__ float g_c2b [BB * 32 * HWs];   // conv2 partial (ic 32..63)
__device__ float g_cost[BB * 32 * HWs];
__device__ float g_norm[BB * 32 * HWs];

// =================================================================================
// Fused q/k/v GEMM, double-buffered smem + register prefetch, 1 sync/chunk.
// M=64, K=256, N=12288. BM=64 BN=64 BK=16, 128 threads. A duplicated [k][2m].
// =================================================================================
__global__ void gemm_qkv_kernel(const float* __restrict__ qw, const float* __restrict__ qb,
                                const float* __restrict__ kw, const float* __restrict__ kb,
                                const float* __restrict__ vw, const float* __restrict__ vb,
                                const float* __restrict__ tf, const float* __restrict__ sf,
                                float* __restrict__ yq, float* __restrict__ yk,
                                float* __restrict__ yv) {
    __shared__ __align__(16) float As2[2 * 16 * 132];
    __shared__ __align__(16) float Bs [2 * 16 * 64];

    const int which = blockIdx.y;
    const float* A    = (which == 0) ? qw : (which == 1) ? kw : vw;
    const float* bias = (which == 0) ? qb : (which == 1) ? kb : vb;
    const float* X    = (which == 0) ? tf : sf;
    float*       Y    = (which == 0) ? yq : (which == 1) ? yk : yv;

    const int b   = blockIdx.z;
    const int n0  = blockIdx.x * 64;
    const int tid = threadIdx.x;
    const int trow = tid >> 3;
    const int tcol = tid & 7;

    const float* Xb = X + (size_t)b * CC * HWs;

    ull acc[4][4];
#pragma unroll
    for (int i = 0; i < 4; ++i)
#pragma unroll
        for (int j = 0; j < 4; ++j) acc[i][j] = 0ull;

    float a_r[8], b_r[8];
    // prologue: chunk 0 -> regs -> buf 0
#pragma unroll
    for (int i = 0; i < 8; ++i) {
        int idx = i * 128 + tid;
        a_r[i] = A[(idx >> 4) * 256 + (idx & 15)];
        b_r[i] = Xb[(size_t)(idx >> 6) * HWs + n0 + (idx & 63)];
    }
#pragma unroll
    for (int i = 0; i < 8; ++i) {
        int idx = i * 128 + tid;
        int m = idx >> 4, k = idx & 15;
        *(ull*)&As2[k * 132 + 2 * m] = f2_pack(a_r[i], a_r[i]);
        Bs[(idx >> 6) * 64 + (idx & 63)] = b_r[i];
    }
    __syncthreads();

    for (int c = 0; c < 16; ++c) {
        if (c < 15) {
            int k0n = (c + 1) * 16;
#pragma unroll
            for (int i = 0; i < 8; ++i) {
                int idx = i * 128 + tid;
                a_r[i] = A[(idx >> 4) * 256 + k0n + (idx & 15)];
                b_r[i] = Xb[(size_t)(k0n + (idx >> 6)) * HWs + n0 + (idx & 63)];
            }
        }
        const float* Asb = As2 + (c & 1) * 2112;
        const float* Bsb = Bs  + (c & 1) * 1024;
#pragma unroll
        for (int kk = 0; kk < 16; ++kk) {
            ulonglong2 a01 = *(const ulonglong2*)&Asb[kk * 132 + trow * 8];
            ulonglong2 a23 = *(const ulonglong2*)&Asb[kk * 132 + trow * 8 + 4];
            ulonglong2 b01 = *(const ulonglong2*)&Bsb[kk * 64 + tcol * 8];
            ulonglong2 b23 = *(const ulonglong2*)&Bsb[kk * 64 + tcol * 8 + 4];
            f2_fma(acc[0][0], a01.x, b01.x); f2_fma(acc[0][1], a01.x, b01.y);
            f2_fma(acc[0][2], a01.x, b23.x); f2_fma(acc[0][3], a01.x, b23.y);
            f2_fma(acc[1][0], a01.y, b01.x); f2_fma(acc[1][1], a01.y, b01.y);
            f2_fma(acc[1][2], a01.y, b23.x); f2_fma(acc[1][3], a01.y, b23.y);
            f2_fma(acc[2][0], a23.x, b01.x); f2_fma(acc[2][1], a23.x, b01.y);
            f2_fma(acc[2][2], a23.x, b23.x); f2_fma(acc[2][3], a23.x, b23.y);
            f2_fma(acc[3][0], a23.y, b01.x); f2_fma(acc[3][1], a23.y, b01.y);
            f2_fma(acc[3][2], a23.y, b23.x); f2_fma(acc[3][3], a23.y, b23.y);
        }
        if (c < 15) {
            float* Asn = As2 + ((c + 1) & 1) * 2112;
            float* Bsn = Bs  + ((c + 1) & 1) * 1024;
#pragma unroll
            for (int i = 0; i < 8; ++i) {
                int idx = i * 128 + tid;
                int m = idx >> 4, k = idx & 15;
                *(ull*)&Asn[k * 132 + 2 * m] = f2_pack(a_r[i], a_r[i]);
                Bsn[(idx >> 6) * 64 + (idx & 63)] = b_r[i];
            }
        }
        __syncthreads();
    }
#pragma unroll
    for (int i = 0; i < 4; ++i) {
        int m = trow * 4 + i;
        float bi = bias[m];
        float* dst = Y + ((size_t)(b * 64 + m)) * HWs + n0 + tcol * 8;
        float v[8];
#pragma unroll
        for (int j = 0; j < 4; ++j) {
            f2_unpack(acc[i][j], v[2 * j], v[2 * j + 1]);
            v[2 * j] += bi; v[2 * j + 1] += bi;
        }
        *(float4*)&dst[0] = make_float4(v[0], v[1], v[2], v[3]);
        *(float4*)&dst[4] = make_float4(v[4], v[5], v[6], v[7]);
    }
}

// =================================================================================
// Final GEMM: M=256, K=288, N=12288, same pipelined structure. 18 chunks.
// =================================================================================
__global__ void gemm_final_kernel(const float* __restrict__ A,
                                  const float* __restrict__ bias,
                                  const float* __restrict__ tfeat,
                                  const float* __restrict__ nrm,
                                  float* __restrict__ Y) {
    __shared__ __align__(16) float As2[2 * 16 * 132];
    __shared__ __align__(16) float Bs [2 * 16 * 64];

    const int b   = blockIdx.z;
    const int n0  = blockIdx.x * 64;
    const int m0  = blockIdx.y * 64;
    const int tid = threadIdx.x;
    const int trow = tid >> 3;
    const int tcol = tid & 7;

    ull acc[4][4];
#pragma unroll
    for (int i = 0; i < 4; ++i)
#pragma unroll
        for (int j = 0; j < 4; ++j) acc[i][j] = 0ull;

    float a_r[8], b_r[8];
#pragma unroll
    for (int i = 0; i < 8; ++i) {
        int idx = i * 128 + tid;
        a_r[i] = A[(m0 + (idx >> 4)) * 288 + (idx & 15)];
        int kg = idx >> 6;
        b_r[i] = tfeat[((size_t)(b * 256 + kg)) * HWs + n0 + (idx & 63)];
    }
#pragma unroll
    for (int i = 0; i < 8; ++i) {
        int idx = i * 128 + tid;
        int m = idx >> 4, k = idx & 15;
        *(ull*)&As2[k * 132 + 2 * m] = f2_pack(a_r[i], a_r[i]);
        Bs[(idx >> 6) * 64 + (idx & 63)] = b_r[i];
    }
    __syncthreads();

    for (int c = 0; c < 18; ++c) {
        if (c < 17) {
            int k0n = (c + 1) * 16;
#pragma unroll
            for (int i = 0; i < 8; ++i) {
                int idx = i * 128 + tid;
                a_r[i] = A[(m0 + (idx >> 4)) * 288 + k0n + (idx & 15)];
                int kg = k0n + (idx >> 6);
                const float* src = (kg < 256)
                    ? (tfeat + ((size_t)(b * 256 + kg)) * HWs)
                    : (nrm + ((size_t)(b * 32 + (kg - 256))) * HWs);
                b_r[i] = src[n0 + (idx & 63)];
            }
        }
        const float* Asb = As2 + (c & 1) * 2112;
        const float* Bsb = Bs  + (c & 1) * 1024;
#pragma unroll
        for (int kk = 0; kk < 16; ++kk) {
            ulonglong2 a01 = *(const ulonglong2*)&Asb[kk * 132 + trow * 8];
            ulonglong2 a23 = *(const ulonglong2*)&Asb[kk * 132 + trow * 8 + 4];
            ulonglong2 b01 = *(const ulonglong2*)&Bsb[kk * 64 + tcol * 8];
            ulonglong2 b23 = *(const ulonglong2*)&Bsb[kk * 64 + tcol * 8 + 4];
            f2_fma(acc[0][0], a01.x, b01.x); f2_fma(acc[0][1], a01.x, b01.y);
            f2_fma(acc[0][2], a01.x, b23.x); f2_fma(acc[0][3], a01.x, b23.y);
            f2_fma(acc[1][0], a01.y, b01.x); f2_fma(acc[1][1], a01.y, b01.y);
            f2_fma(acc[1][2], a01.y, b23.x); f2_fma(acc[1][3], a01.y, b23.y);
            f2_fma(acc[2][0], a23.x, b01.x); f2_fma(acc[2][1], a23.x, b01.y);
            f2_fma(acc[2][2], a23.x, b23.x); f2_fma(acc[2][3], a23.x, b23.y);
            f2_fma(acc[3][0], a23.y, b01.x); f2_fma(acc[3][1], a23.y, b01.y);
            f2_fma(acc[3][2], a23.y, b23.x); f2_fma(acc[3][3], a23.y, b23.y);
        }
        if (c < 17) {
            float* Asn = As2 + ((c + 1) & 1) * 2112;
            float* Bsn = Bs  + ((c + 1) & 1) * 1024;
#pragma unroll
            for (int i = 0; i < 8; ++i) {
                int idx = i * 128 + tid;
                int m = idx >> 4, k = idx & 15;
                *(ull*)&Asn[k * 132 + 2 * m] = f2_pack(a_r[i], a_r[i]);
                Bsn[(idx >> 6) * 64 + (idx & 63)] = b_r[i];
            }
        }
        __syncthreads();
    }
#pragma unroll
    for (int i = 0; i < 4; ++i) {
        int m = m0 + trow * 4 + i;
        float bi = bias[m];
        float* dst = Y + ((size_t)(b * 256 + m)) * HWs + n0 + tcol * 8;
        float v[8];
#pragma unroll
        for (int j = 0; j < 4; ++j) f2_unpack(acc[i][j], v[2 * j], v[2 * j + 1]);
#pragma unroll
        for (int j = 0; j < 8; ++j) {
            v[j] += bi;
            v[j] = v[j] > 0.f ? v[j] : (__expf(v[j]) - 1.f);
        }
        *(float4*)&dst[0] = make_float4(v[0], v[1], v[2], v[3]);
        *(float4*)&dst[4] = make_float4(v[4], v[5], v[6], v[7]);
    }
}

// =================================================================================
// Fused warp + cost + softmax + aggregation (unchanged).
// =================================================================================
__global__ void attn_kernel(const float* __restrict__ gq,
                            const float* __restrict__ gk,
                            const float* __restrict__ gv,
                            const float* __restrict__ directs,
                            const int*   __restrict__ img_w_i,
                            float* __restrict__ gcost,
                            float* __restrict__ gagg) {
    extern __shared__ float sm[];
    float* ks = sm;
    float* vs = ks + 64 * KSTR;

    const int h = blockIdx.x;
    const int b = blockIdx.y;
    const int w = threadIdx.x;

    const size_t base = ((size_t)(b * 64)) * HWs + h * WW + w;

    for (int c = 0; c < 64; ++c) {
        size_t off = base + (size_t)c * HWs;
        float kv = gk[off];
        float vv = gv[off];
        ks[c * KSTR + w] = kv;
        vs[c * KSTR + w] = vv;
        if (w == WW - 1) {
            ks[c * KSTR + WW] = kv;
            vs[c * KSTR + WW] = vv;
        }
    }

    int iv = img_w_i[0];
    float imw = (iv > 0 && iv < 1000000) ? (float)iv : __int_as_float(iv);
    float ss = directs[b] * (640.0f / imw) * (0.01f * (float)(WW - 1));

    int   ix[DD];
    float fr[DD];
#pragma unroll
    for (int d = 0; d < DD; ++d) {
        float src = fminf(fmaxf((float)w + ss * (float)d, 0.0f), (float)(WW - 1));
        float x0 = floorf(src);
        ix[d] = (int)x0;
        fr[d] = src - x0;
    }
    __syncthreads();

    float cost[DD];
#pragma unroll
    for (int d = 0; d < DD; ++d) cost[d] = 0.f;

    float qn = gq[base];
    for (int c = 0; c < 64; ++c) {
        float qc = qn;
        if (c + 1 < 64) qn = gq[base + (size_t)(c + 1) * HWs];
        const float* kr = ks + c * KSTR;
#pragma unroll
        for (int d = 0; d < DD; ++d) {
            float k0 = kr[ix[d]];
            float k1 = kr[ix[d] + 1];
            cost[d] += qc * (k0 + fr[d] * (k1 - k0));
        }
    }
#pragma unroll
    for (int d = 0; d < DD; ++d) {
        cost[d] *= 0.125f;
        gcost[((size_t)(b * 32 + d)) * HWs + h * WW + w] = cost[d];
    }

    float mx = cost[0];
#pragma unroll
    for (int d = 1; d < DD; ++d) mx = fmaxf(mx, cost[d]);
    float s = 0.f;
#pragma unroll
    for (int d = 0; d < DD; ++d) { cost[d] = __expf(cost[d] - mx); s += cost[d]; }
    float inv = 1.0f / s;
#pragma unroll
    for (int d = 0; d < DD; ++d) cost[d] *= inv;

    for (int c = 0; c < 64; ++c) {
        const float* vr = vs + c * KSTR;
        float acc = 0.f;
#pragma unroll
        for (int d = 0; d < DD; ++d) {
            float v0 = vr[ix[d]];
            float v1 = vr[ix[d] + 1];
            acc += cost[d] * (v0 + fr[d] * (v1 - v0));
        }
        gagg[base + (size_t)c * HWs] = acc;
    }
}

// =================================================================================
// conv3x3 #1 SPLIT-K, double-buffered staging, 1 sync/chunk (8 chunks of 8 ic).
// in_s buf stride 2016 (8*252), w_s buf stride 4896 (72*68).
// =================================================================================
__global__ void conv1_kernel(const float* __restrict__ gq,
                             const float* __restrict__ gagg,
                             const float* __restrict__ wgt,   // [64][128][3][3]
                             float* __restrict__ outa,
                             float* __restrict__ outb) {
    __shared__ __align__(16) float in_s[2 * 8 * 252];
    __shared__ __align__(16) float w_s [2 * 72 * 68];

    const int bz  = blockIdx.z;
    const int b   = bz >> 1;
    const int ks  = bz & 1;
    const int y0  = blockIdx.y * 11;
    const int tx0 = blockIdx.x * 16;
    const int tid = threadIdx.x;
    const int ocg = tid >> 6;
    const int pix = tid & 63;

    const float* src_base = (ks == 0) ? gq : gagg;
    float* out = (ks == 0) ? outa : outb;

    int py_[3], px_[3];
    bool val_[3];
#pragma unroll
    for (int k = 0; k < 3; ++k) {
        int l = pix + 64 * k;
        py_[k] = l >> 4;
        px_[k] = l & 15;
        val_[k] = (l < 176);
    }

    ull acc[3][8];
#pragma unroll
    for (int k = 0; k < 3; ++k)
#pragma unroll
        for (int j = 0; j < 8; ++j) acc[k][j] = 0ull;

    float in_r[8];
    float w_r[18];

    // ---- prologue: chunk 0 -> regs -> buf 0 ----
#pragma unroll
    for (int i = 0; i < 8; ++i) {
        int idx = i * 256 + tid;
        float v = 0.f;
        if (idx < 1872) {
            int ic = idx / 234;
            int r  = idx - ic * 234;
            int yy = r / 18, xx = r - yy * 18;
            int gy = y0 + yy - 1, gx = tx0 + xx - 1;
            if ((unsigned)gy < (unsigned)HH && (unsigned)gx < (unsigned)WW)
                v = src_base[((size_t)(b * 64 + ic)) * HWs + gy * WW + gx];
        }
        in_r[i] = v;
    }
#pragma unroll
    for (int i = 0; i < 18; ++i) {
        int idx = i * 256 + tid;
        int oc = idx / 72, t = idx - oc * 72;
        int ic = t / 9,  r9 = t - ic * 9;
        w_r[i] = wgt[((oc * 128) + ks * 64 + ic) * 9 + r9];
    }
#pragma unroll
    for (int i = 0; i < 8; ++i) {
        int idx = i * 256 + tid;
        if (idx < 1872) {
            int ic = idx / 234;
            in_s[ic * 252 + (idx - ic * 234)] = in_r[i];
        }
    }
#pragma unroll
    for (int i = 0; i < 18; ++i) {
        int idx = i * 256 + tid;
        int oc = idx / 72, t = idx - oc * 72;
        w_s[t * 68 + oc] = w_r[i];
    }
    __syncthreads();

    for (int cc = 0; cc < 8; ++cc) {
        if (cc < 7) {
            int c0 = (cc + 1) * 8;
#pragma unroll
            for (int i = 0; i < 8; ++i) {
                int idx = i * 256 + tid;
                float v = 0.f;
                if (idx < 1872) {
                    int ic = idx / 234;
                    int r  = idx - ic * 234;
                    int yy = r / 18, xx = r - yy * 18;
                    int gy = y0 + yy - 1, gx = tx0 + xx - 1;
                    if ((unsigned)gy < (unsigned)HH && (unsigned)gx < (unsigned)WW)
                        v = src_base[((size_t)(b * 64 + c0 + ic)) * HWs + gy * WW + gx];
                }
                in_r[i] = v;
            }
#pragma unroll
            for (int i = 0; i < 18; ++i) {
                int idx = i * 256 + tid;
                int oc = idx / 72, t = idx - oc * 72;
                int ic = t / 9,  r9 = t - ic * 9;
                w_r[i] = wgt[((oc * 128) + ks * 64 + c0 + ic) * 9 + r9];
            }
        }
        const float* inb = in_s + (cc & 1) * 2016;
        const float* wb  = w_s  + (cc & 1) * 4896;
#pragma unroll 1
        for (int ic = 0; ic < 8; ++ic) {
#pragma unroll
            for (int ky = 0; ky < 3; ++ky)
#pragma unroll
            for (int kx = 0; kx < 3; ++kx) {
                int t = ic * 9 + ky * 3 + kx;
                ulonglong2 w01 = *(const ulonglong2*)&wb[t * 68 + ocg * 16];
                ulonglong2 w23 = *(const ulonglong2*)&wb[t * 68 + ocg * 16 + 4];
                ulonglong2 w45 = *(const ulonglong2*)&wb[t * 68 + ocg * 16 + 8];
                ulonglong2 w67 = *(const ulonglong2*)&wb[t * 68 + ocg * 16 + 12];
#pragma unroll
                for (int k = 0; k < 3; ++k) {
                    float ivv = inb[ic * 252 + (py_[k] + ky) * 18 + px_[k] + kx];
                    ull iv2 = f2_pack(ivv, ivv);
                    f2_fma(acc[k][0], iv2, w01.x); f2_fma(acc[k][1], iv2, w01.y);
                    f2_fma(acc[k][2], iv2, w23.x); f2_fma(acc[k][3], iv2, w23.y);
                    f2_fma(acc[k][4], iv2, w45.x); f2_fma(acc[k][5], iv2, w45.y);
                    f2_fma(acc[k][6], iv2, w67.x); f2_fma(acc[k][7], iv2, w67.y);
                }
            }
        }
        if (cc < 7) {
            float* inn = in_s + ((cc + 1) & 1) * 2016;
            float* wn  = w_s  + ((cc + 1) & 1) * 4896;
#pragma unroll
            for (int i = 0; i < 8; ++i) {
                int idx = i * 256 + tid;
                if (idx < 1872) {
                    int ic = idx / 234;
                    inn[ic * 252 + (idx - ic * 234)] = in_r[i];
                }
            }
#pragma unroll
            for (int i = 0; i < 18; ++i) {
                int idx = i * 256 + tid;
                int oc = idx / 72, t = idx - oc * 72;
                wn[t * 68 + oc] = w_r[i];
            }
        }
        __syncthreads();
    }
#pragma unroll
    for (int k = 0; k < 3; ++k) {
        int gy = y0 + py_[k], gx = tx0 + px_[k];
        if (!val_[k] || gy >= HH) continue;
#pragma unroll
        for (int j = 0; j < 8; ++j) {
            int oc = ocg * 16 + 2 * j;
            float v0, v1;
            f2_unpack(acc[k][j], v0, v1);
            out[((size_t)(b * 64 + oc)) * HWs + gy * WW + gx]     = v0;
            out[((size_t)(b * 64 + oc + 1)) * HWs + gy * WW + gx] = v1;
        }
    }
}

// =================================================================================
// conv3x3 #2 SPLIT-K, double-buffered staging (4 chunks of 8 ic).
// Staging fuses conv1 combine: h1 = elu(p0 + p1 + bias1).
// Single shared array so exchange-phase reuse (256*33 floats) is well-defined.
// =================================================================================
__global__ void conv2_kernel(const float* __restrict__ p0,
                             const float* __restrict__ p1,
                             const float* __restrict__ bias1,  // p1b [64]
                             const float* __restrict__ wgt,    // [32][64][3][3]
                             float* __restrict__ c2a,
                             float* __restrict__ c2b) {
    __shared__ __align__(16) float smem_all[9216];  // in_s 2*2016 | w_s 2*2592
    float* in_s = smem_all;            // 4032 floats
    float* w_s  = smem_all + 4032;     // 5184 floats

    const int bz  = blockIdx.z;
    const int b   = bz >> 1;
    const int ks  = bz & 1;
    const int y0  = blockIdx.y * 11;
    const int tx0 = blockIdx.x * 16;
    const int tid = threadIdx.x;
    const int ocg  = tid >> 7;
    const int pixg = tid & 127;

    float* outp = (ks == 0) ? c2a : c2b;

    ull acc[2][8];
#pragma unroll
    for (int k = 0; k < 2; ++k)
#pragma unroll
        for (int j = 0; j < 8; ++j) acc[k][j] = 0ull;

    float in_r[8];
    float w_r[9];

    // ---- prologue: chunk 0 ----
#pragma unroll
    for (int i = 0; i < 8; ++i) {
        int idx = i * 256 + tid;
        float v = 0.f;
        if (idx < 1872) {
            int ic = idx / 234;
            int r  = idx - ic * 234;
            int yy = r / 18, xx = r - yy * 18;
            int gy = y0 + yy - 1, gx = tx0 + xx - 1;
            if ((unsigned)gy < (unsigned)HH && (unsigned)gx < (unsigned)WW) {
                int icg = ks * 32 + ic;
                size_t off = ((size_t)(b * 64 + icg)) * HWs + gy * WW + gx;
                float t = p0[off] + p1[off] + bias1[icg];
                v = t > 0.f ? t : (__expf(t) - 1.f);
            }
        }
        in_r[i] = v;
    }
#pragma unroll
    for (int i = 0; i < 9; ++i) {
        int idx = i * 256 + tid;
        int oc = idx / 72, t = idx - oc * 72;
        int ic = t / 9,  r9 = t - ic * 9;
        w_r[i] = wgt[((oc * 64) + ks * 32 + ic) * 9 + r9];
    }
#pragma unroll
    for (int i = 0; i < 8; ++i) {
        int idx = i * 256 + tid;
        if (idx < 1872) {
            int ic = idx / 234;
            in_s[ic * 252 + (idx - ic * 234)] = in_r[i];
        }
    }
#pragma unroll
    for (int i = 0; i < 9; ++i) {
        int idx = i * 256 + tid;
        int oc = idx / 72, t = idx - oc * 72;
        w_s[t * 36 + oc] = w_r[i];
    }
    __syncthreads();

    for (int cc = 0; cc < 4; ++cc) {
        if (cc < 3) {
            int c0 = (cc + 1) * 8;
#pragma unroll
            for (int i = 0; i < 8; ++i) {
                int idx = i * 256 + tid;
                float v = 0.f;
                if (idx < 1872) {
                    int ic = idx / 234;
                    int r  = idx - ic * 234;
                    int yy = r / 18, xx = r - yy * 18;
                    int gy = y0 + yy - 1, gx = tx0 + xx - 1;
                    if ((unsigned)gy < (unsigned)HH && (unsigned)gx < (unsigned)WW) {
                        int icg = ks * 32 + c0 + ic;
                        size_t off = ((size_t)(b * 64 + icg)) * HWs + gy * WW + gx;
                        float t = p0[off] + p1[off] + bias1[icg];
                        v = t > 0.f ? t : (__expf(t) - 1.f);
                    }
                }
                in_r[i] = v;
            }
#pragma unroll
            for (int i = 0; i < 9; ++i) {
                int idx = i * 256 + tid;
                int oc = idx / 72, t = idx - oc * 72;
                int ic = t / 9,  r9 = t - ic * 9;
                w_r[i] = wgt[((oc * 64) + ks * 32 + c0 + ic) * 9 + r9];
            }
        }
        const float* inb = in_s + (cc & 1) * 2016;
        const float* wb  = w_s  + (cc & 1) * 2592;
#pragma unroll 1
        for (int ic = 0; ic < 8; ++ic) {
#pragma unroll
            for (int ky = 0; ky < 3; ++ky)
#pragma unroll
            for (int kx = 0; kx < 3; ++kx) {
                int t = ic * 9 + ky * 3 + kx;
                ulonglong2 w01 = *(const ulonglong2*)&wb[t * 36 + ocg * 16];
                ulonglong2 w23 = *(const ulonglong2*)&wb[t * 36 + ocg * 16 + 4];
                ulonglong2 w45 = *(const ulonglong2*)&wb[t * 36 + ocg * 16 + 8];
                ulonglong2 w67 = *(const ulonglong2*)&wb[t * 36 + ocg * 16 + 12];
#pragma unroll
                for (int k = 0; k < 2; ++k) {
                    int l = pixg + 128 * k;
                    int py = l >> 4, px = l & 15;
                    float ivv = inb[ic * 252 + (py + ky) * 18 + px + kx];
                    ull iv2 = f2_pack(ivv, ivv);
                    f2_fma(acc[k][0], iv2, w01.x); f2_fma(acc[k][1], iv2, w01.y);
                    f2_fma(acc[k][2], iv2, w23.x); f2_fma(acc[k][3], iv2, w23.y);
                    f2_fma(acc[k][4], iv2, w45.x); f2_fma(acc[k][5], iv2, w45.y);
                    f2_fma(acc[k][6], iv2, w67.x); f2_fma(acc[k][7], iv2, w67.y);
                }
            }
        }
        if (cc < 3) {
            float* inn = in_s + ((cc + 1) & 1) * 2016;
            float* wn  = w_s  + ((cc + 1) & 1) * 2592;
#pragma unroll
            for (int i = 0; i < 8; ++i) {
                int idx = i * 256 + tid;
                if (idx < 1872) {
                    int ic = idx / 234;
                    inn[ic * 252 + (idx - ic * 234)] = in_r[i];
                }
            }
#pragma unroll
            for (int i = 0; i < 9; ++i) {
                int idx = i * 256 + tid;
                int oc = idx / 72, t = idx - oc * 72;
                wn[t * 36 + oc] = w_r[i];
            }
        }
        __syncthreads();
    }

    // exchange: reuse whole smem_all (9216 >= 256*33=8448), all staging done
    float* xbuf = smem_all;
    __syncthreads();
#pragma unroll
    for (int k = 0; k < 2; ++k) {
        int l = pixg + 128 * k;
#pragma unroll
        for (int j = 0; j < 8; ++j) {
            float v0, v1;
            f2_unpack(acc[k][j], v0, v1);
            int oc = ocg * 16 + 2 * j;
            xbuf[l * 33 + oc]     = v0;
            xbuf[l * 33 + oc + 1] = v1;
        }
    }
    __syncthreads();

    if (tid < 176) {
        int py = tid >> 4, px = tid & 15;
        int gy = y0 + py, gx = tx0 + px;
        if (gy < HH) {
            size_t pbase = (size_t)b * 32 * HWs + gy * WW + gx;
#pragma unroll
            for (int d = 0; d < 32; ++d)
                outp[pbase + (size_t)d * HWs] = xbuf[tid * 33 + d];
        }
    }
}

// =================================================================================
// Combine: cost merge + softmax (unchanged).
// =================================================================================
__global__ void combine_kernel(const float* __restrict__ c2a,
                               const float* __restrict__ c2b,
                               const float* __restrict__ bias2,
                               const float* __restrict__ gcost,
                               float* __restrict__ out_cost,
                               float* __restrict__ gnorm) {
    const int b = blockIdx.y;
    const int p = blockIdx.x * 256 + threadIdx.x;
    size_t base = (size_t)b * 32 * HWs + p;

    float cn[32];
    float mx = -1e30f;
#pragma unroll
    for (int d = 0; d < 32; ++d) {
        size_t off = base + (size_t)d * HWs;
        float r = c2a[off] + c2b[off] + bias2[d];
        float v = 0.5f * (gcost[off] + r);
        cn[d] = v;
        mx = fmaxf(mx, v);
        out_cost[off] = v;
    }
    float s = 0.f;
#pragma unroll
    for (int d = 0; d < 32; ++d) { cn[d] = __expf(cn[d] - mx); s += cn[d]; }
    float inv = 1.f / s;
#pragma unroll
    for (int d = 0; d < 32; ++d) gnorm[base + (size_t)d * HWs] = cn[d] * inv;
}

// =================================================================================
extern "C" void kernel_launch(void* const* d_in, const int* in_sizes, int n_in,
                              void* d_out, int out_size) {
    (void)in_sizes; (void)n_in; (void)out_size;
    const float* t_feat  = (const float*)d_in[0];
    const float* s_feat  = (const float*)d_in[1];
    const float* directs = (const float*)d_in[2];
    const float* qw = (const float*)d_in[3];
    const float* qb = (const float*)d_in[4];
    const float* kw = (const float*)d_in[5];
    const float* kb = (const float*)d_in[6];
    const float* vw = (const float*)d_in[7];
    const float* vb = (const float*)d_in[8];
    const float* p1w = (const float*)d_in[9];
    const float* p1b = (const float*)d_in[10];
    const float* p2w = (const float*)d_in[11];
    const float* p2b = (const float*)d_in[12];
    const float* rw  = (const float*)d_in[13];
    const float* rb  = (const float*)d_in[14];
    const int*   img_w = (const int*)d_in[15];

    float* out_x    = (float*)d_out;
    float* out_cost = out_x + (size_t)BB * CC * HWs;

    float *pq, *pk, *pv, *pagg, *ph1a, *ph1b, *pc2a, *pc2b, *pcost, *pnorm;
    cudaGetSymbolAddress((void**)&pq,    g_q);
    cudaGetSymbolAddress((void**)&pk,    g_k);
    cudaGetSymbolAddress((void**)&pv,    g_v);
    cudaGetSymbolAddress((void**)&pagg,  g_agg);
    cudaGetSymbolAddress((void**)&ph1a,  g_h1a);
    cudaGetSymbolAddress((void**)&ph1b,  g_h1b);
    cudaGetSymbolAddress((void**)&pc2a,  g_c2a);
    cudaGetSymbolAddress((void**)&pc2b,  g_c2b);
    cudaGetSymbolAddress((void**)&pcost, g_cost);
    cudaGetSymbolAddress((void**)&pnorm, g_norm);

    // fused q/k/v 1x1 convs (pipelined)
    gemm_qkv_kernel<<<dim3(192, 3, BB), 128>>>(qw, qb, kw, kb, vw, vb,
                                               t_feat, s_feat, pq, pk, pv);

    // fused warp/cost/softmax/agg
    const int attn_smem = (64 * KSTR * 2) * (int)sizeof(float);  // 98816
    cudaFuncSetAttribute(attn_kernel, cudaFuncAttributeMaxDynamicSharedMemorySize,
                         attn_smem);
    attn_kernel<<<dim3(HH, BB), WW, attn_smem>>>(pq, pk, pv, directs, img_w,
                                                 pcost, pagg);

    // conv3x3 #1 split-K, pipelined
    conv1_kernel<<<dim3(12, 6, BB * 2), 256>>>(pq, pagg, p1w, ph1a, ph1b);
    // conv3x3 #2 split-K, pipelined (staging fuses conv1 bias+ELU)
    conv2_kernel<<<dim3(12, 6, BB * 2), 256>>>(ph1a, ph1b, p1b, p2w, pc2a, pc2b);
    // combine: cost merge + softmax
    combine_kernel<<<dim3(48, BB), 256>>>(pc2a, pc2b, p2b, pcost, out_cost, pnorm);

    // final 1x1 (288 -> 256) + ELU, pipelined
    gemm_final_kernel<<<dim3(192, 4, BB), 128>>>(rw, rb, t_feat, pnorm, out_x);
}